// round 1
// baseline (speedup 1.0000x reference)
#include <cuda_runtime.h>
#include <math.h>

#define B_    2
#define S_    2048
#define D_    2048
#define H_    16
#define NT    4096          // B_*S_
#define QL    1024
#define KVL   512
#define NOPE_ 128
#define ROPE_ 64
#define VH_   128
#define QK_   192
#define KFW   576           // KVL + ROPE
#define HQK   3072          // H_*QK_
#define HQF   9216          // H_*KFW
#define SCALE 0.07216878364870322f   // 192^-0.5

// ---------------- scratch (static device globals; no runtime alloc) -------
__device__ float g_qa[(size_t)NT * QL];                 // 16 MB
__device__ float g_q [(size_t)NT * HQK];                // 48 MB
__device__ float g_kvfull[(size_t)NT * KFW];            // 9.4 MB
__device__ float g_qf[(size_t)NT * HQF];                // 151 MB  [qnope_proj(512)|q_pe_rope(64)] per head
__device__ float g_kf[(size_t)NT * KFW];                // 9.4 MB  [kv_c(512)|k_pe_rope(64)]
__device__ float g_scores[(size_t)B_ * H_ * S_ * S_];   // 536 MB
__device__ float g_omid[(size_t)NT * H_ * KVL];         // 134 MB
__device__ float g_ocat[(size_t)NT * H_ * VH_];         // 33.5 MB

// ---------------- generic batched tiled GEMM -------------------------------
// C[z] = alpha * A[z] @ op(B[z]) + bias
// TB=true : B is [N,K] row-major (op = B^T)  -> C = A @ B^T
// TB=false: B is [K,N] row-major             -> C = A @ B
// z = blockIdx.z decomposed as (zb, zh) with zh = z % ZH.
template<bool TB>
__global__ void __launch_bounds__(256) gemm_k(
    int M, int N, int K,
    const float* __restrict__ A, int lda, long long sAb, long long sAh,
    const float* __restrict__ Bp, int ldb, long long sBb, long long sBh,
    float* __restrict__ C, int ldc, long long sCb, long long sCh,
    int ZH, float alpha, const float* __restrict__ bias)
{
    __shared__ __align__(16) float As[16][64];
    __shared__ __align__(16) float Bs[16][64];

    int z  = blockIdx.z;
    int zb = z / ZH;
    int zh = z - zb * ZH;
    const float* Ab = A  + zb * sAb + zh * sAh;
    const float* Bb = Bp + zb * sBb + zh * sBh;
    float*       Cb = C  + zb * sCb + zh * sCh;

    int row0 = blockIdx.y << 6;
    int col0 = blockIdx.x << 6;
    int tid  = threadIdx.x;

    // A loader: 4 consecutive k per thread
    int am = tid >> 2, ak = (tid & 3) << 2;
    const float* aptr = Ab + (size_t)(row0 + am) * lda + ak;

    int ty = tid >> 4, tx = tid & 15;
    float acc[4][4] = {};

    for (int k0 = 0; k0 < K; k0 += 16) {
        float4 av = *(const float4*)(aptr + k0);
        As[ak + 0][am] = av.x;
        As[ak + 1][am] = av.y;
        As[ak + 2][am] = av.z;
        As[ak + 3][am] = av.w;

        if (TB) {
            int bn = tid >> 2, bk = (tid & 3) << 2;
            float4 bv = *(const float4*)(Bb + (size_t)(col0 + bn) * ldb + k0 + bk);
            Bs[bk + 0][bn] = bv.x;
            Bs[bk + 1][bn] = bv.y;
            Bs[bk + 2][bn] = bv.z;
            Bs[bk + 3][bn] = bv.w;
        } else {
            int bk = tid >> 4, bn4 = (tid & 15) << 2;
            *(float4*)&Bs[bk][bn4] =
                *(const float4*)(Bb + (size_t)(k0 + bk) * ldb + col0 + bn4);
        }
        __syncthreads();

        #pragma unroll
        for (int kk = 0; kk < 16; kk++) {
            float4 a4 = *(const float4*)&As[kk][ty << 2];
            float4 b4 = *(const float4*)&Bs[kk][tx << 2];
            float ar[4] = {a4.x, a4.y, a4.z, a4.w};
            float br[4] = {b4.x, b4.y, b4.z, b4.w};
            #pragma unroll
            for (int i = 0; i < 4; i++)
                #pragma unroll
                for (int j = 0; j < 4; j++)
                    acc[i][j] += ar[i] * br[j];
        }
        __syncthreads();
    }

    #pragma unroll
    for (int i = 0; i < 4; i++) {
        size_t roff = (size_t)(row0 + (ty << 2) + i) * ldc + col0 + (tx << 2);
        #pragma unroll
        for (int j = 0; j < 4; j++) {
            float v = alpha * acc[i][j];
            if (bias) v += bias[col0 + (tx << 2) + j];
            Cb[roff + j] = v;
        }
    }
}

// ---------------- rmsnorm ---------------------------------------------------
__global__ void rmsnorm_k(const float* __restrict__ in, float* __restrict__ out,
                          const float* __restrict__ w, int width,
                          int inStride, int outStride)
{
    int row = blockIdx.x;
    const float* ip = in  + (size_t)row * inStride;
    float*       op = out + (size_t)row * outStride;
    float ss = 0.f;
    for (int i = threadIdx.x; i < width; i += 256) {
        float v = ip[i];
        ss += v * v;
    }
    __shared__ float sm[256];
    sm[threadIdx.x] = ss;
    __syncthreads();
    for (int s = 128; s > 0; s >>= 1) {
        if (threadIdx.x < s) sm[threadIdx.x] += sm[threadIdx.x + s];
        __syncthreads();
    }
    float r = rsqrtf(sm[0] / (float)width + 1e-3f);
    for (int i = threadIdx.x; i < width; i += 256)
        op[i] = w[i] * ip[i] * r;
}

// ---------------- rope -------------------------------------------------------
__global__ void rope_q_k(const float* __restrict__ q, float* __restrict__ qf,
                         const float* __restrict__ c, const float* __restrict__ s)
{
    int tok = blockIdx.x;
    int h = threadIdx.x >> 5;
    int j = threadIdx.x & 31;
    int pos = tok % S_;
    const float* src = q  + (size_t)tok * HQK + h * QK_ + NOPE_;
    float*       dst = qf + (size_t)tok * HQF + h * KFW + KVL;
    float xr = src[2 * j], xi = src[2 * j + 1];
    float cc = c[pos * 32 + j], sn = s[pos * 32 + j];
    dst[2 * j]     = xr * cc - xi * sn;
    dst[2 * j + 1] = xr * sn + xi * cc;
}

__global__ void rope_k_k(const float* __restrict__ kvf, float* __restrict__ kf,
                         const float* __restrict__ c, const float* __restrict__ s)
{
    int tok = blockIdx.x;
    int j = threadIdx.x;   // 0..31
    int pos = tok % S_;
    const float* src = kvf + (size_t)tok * KFW + KVL;
    float*       dst = kf  + (size_t)tok * KFW + KVL;
    float xr = src[2 * j], xi = src[2 * j + 1];
    float cc = c[pos * 32 + j], sn = s[pos * 32 + j];
    dst[2 * j]     = xr * cc - xi * sn;
    dst[2 * j + 1] = xr * sn + xi * cc;
}

// ---------------- softmax over rows of length S_ ----------------------------
__global__ void softmax_k(float* __restrict__ d)
{
    size_t row = blockIdx.x;
    float* p = d + row * (size_t)S_;
    int t = threadIdx.x;
    float v[8];
    float m = -INFINITY;
    #pragma unroll
    for (int i = 0; i < 8; i++) {
        v[i] = p[t + i * 256];
        m = fmaxf(m, v[i]);
    }
    __shared__ float sm[256];
    sm[t] = m;
    __syncthreads();
    for (int s = 128; s > 0; s >>= 1) {
        if (t < s) sm[t] = fmaxf(sm[t], sm[t + s]);
        __syncthreads();
    }
    m = sm[0];
    __syncthreads();
    float sum = 0.f;
    #pragma unroll
    for (int i = 0; i < 8; i++) {
        v[i] = __expf(v[i] - m);
        sum += v[i];
    }
    sm[t] = sum;
    __syncthreads();
    for (int s = 128; s > 0; s >>= 1) {
        if (t < s) sm[t] += sm[t + s];
        __syncthreads();
    }
    float inv = 1.f / sm[0];
    #pragma unroll
    for (int i = 0; i < 8; i++)
        p[t + i * 256] = v[i] * inv;
}

// ---------------- host glue --------------------------------------------------
template<bool TB>
static void launch_gemm(int M, int N, int K,
                        const float* A, int lda, long long sAb, long long sAh,
                        const float* Bp, int ldb, long long sBb, long long sBh,
                        float* C, int ldc, long long sCb, long long sCh,
                        int nb, int nh, float alpha, const float* bias)
{
    dim3 grid(N / 64, M / 64, nb * nh);
    gemm_k<TB><<<grid, 256>>>(M, N, K, A, lda, sAb, sAh, Bp, ldb, sBb, sBh,
                              C, ldc, sCb, sCh, nh, alpha, bias);
}

extern "C" void kernel_launch(void* const* d_in, const int* in_sizes, int n_in,
                              void* d_out, int out_size)
{
    const float* x        = (const float*)d_in[0];
    // d_in[1] = start_pos (unused by the reference math)
    const float* cosp     = (const float*)d_in[2];
    const float* sinp     = (const float*)d_in[3];
    const float* wq_a_w   = (const float*)d_in[4];
    const float* wq_a_b   = (const float*)d_in[5];
    const float* q_norm_w = (const float*)d_in[6];
    const float* wq_b_w   = (const float*)d_in[7];
    const float* wq_b_b   = (const float*)d_in[8];
    const float* wkv_a_w  = (const float*)d_in[9];
    const float* wkv_a_b  = (const float*)d_in[10];
    const float* kv_norm_w= (const float*)d_in[11];
    const float* wkv_b_w  = (const float*)d_in[12];
    const float* wo_w     = (const float*)d_in[13];
    const float* wo_b     = (const float*)d_in[14];
    float* out = (float*)d_out;

    float *qa, *q, *kvf, *qf, *kf, *sc, *om, *oc;
    cudaGetSymbolAddress((void**)&qa,  g_qa);
    cudaGetSymbolAddress((void**)&q,   g_q);
    cudaGetSymbolAddress((void**)&kvf, g_kvfull);
    cudaGetSymbolAddress((void**)&qf,  g_qf);
    cudaGetSymbolAddress((void**)&kf,  g_kf);
    cudaGetSymbolAddress((void**)&sc,  g_scores);
    cudaGetSymbolAddress((void**)&om,  g_omid);
    cudaGetSymbolAddress((void**)&oc,  g_ocat);

    // 1) q_a = x @ wq_a^T + b          [4096,1024]
    launch_gemm<true>(NT, QL, D_, x, D_, 0, 0, wq_a_w, D_, 0, 0,
                      qa, QL, 0, 0, 1, 1, 1.f, wq_a_b);
    // 2) rmsnorm(q_a) in place
    rmsnorm_k<<<NT, 256>>>(qa, qa, q_norm_w, QL, QL, QL);
    // 3) q = q_a_n @ wq_b^T + b        [4096,3072]
    launch_gemm<true>(NT, HQK, QL, qa, QL, 0, 0, wq_b_w, QL, 0, 0,
                      q, HQK, 0, 0, 1, 1, 1.f, wq_b_b);
    // 4) kv_full = x @ wkv_a^T + b     [4096,576]
    launch_gemm<true>(NT, KFW, D_, x, D_, 0, 0, wkv_a_w, D_, 0, 0,
                      kvf, KFW, 0, 0, 1, 1, 1.f, wkv_a_b);
    // 5) kf[:, :512] = rmsnorm(kv_full[:, :512])
    rmsnorm_k<<<NT, 256>>>(kvf, kf, kv_norm_w, KVL, KFW, KFW);
    // 6) kf[:, 512:576] = rope(k_pe)
    rope_k_k<<<NT, 32>>>(kvf, kf, cosp, sinp);
    // 7) qf[:, h, 512:576] = rope(q_pe)
    rope_q_k<<<NT, 512>>>(q, qf, cosp, sinp);
    // 8) qf[:, h, :512] = q_nope_h @ wkv_b[h,:128,:]   (NN, batched over h)
    launch_gemm<false>(NT, KVL, NOPE_,
                       q, HQK, 0, QK_,
                       wkv_b_w, KVL, 0, (long long)(NOPE_ + VH_) * KVL,
                       qf, HQF, 0, KFW,
                       1, H_, 1.f, nullptr);
    // 9) scores[b,h] = SCALE * qf[b,:,h,:] @ kf[b]^T   [2048,2048] x32
    launch_gemm<true>(S_, S_, KFW,
                      qf, HQF, (long long)S_ * HQF, KFW,
                      kf, KFW, (long long)S_ * KFW, 0,
                      sc, S_, (long long)H_ * S_ * S_, (long long)S_ * S_,
                      B_, H_, SCALE, nullptr);
    // 10) softmax rows
    softmax_k<<<B_ * H_ * S_, 256>>>(sc);
    // 11) o_mid[b,:,h,:] = probs[b,h] @ kv_c[b]        (NN) [2048,512] x32
    launch_gemm<false>(S_, KVL, S_,
                       sc, S_, (long long)H_ * S_ * S_, (long long)S_ * S_,
                       kf, KFW, (long long)S_ * KFW, 0,
                       om, H_ * KVL, (long long)S_ * H_ * KVL, KVL,
                       B_, H_, 1.f, nullptr);
    // 12) o_cat[:, h*128:] = o_mid_h @ wkv_b[h,128:,:]^T  (NT, batched over h)
    launch_gemm<true>(NT, VH_, KVL,
                      om, H_ * KVL, 0, KVL,
                      wkv_b_w + (size_t)NOPE_ * KVL, KVL, 0,
                      (long long)(NOPE_ + VH_) * KVL,
                      oc, H_ * VH_, 0, VH_,
                      1, H_, 1.f, nullptr);
    // 13) out = o_cat @ wo^T + b        [4096,2048]
    launch_gemm<true>(NT, D_, H_ * VH_, oc, H_ * VH_, 0, 0, wo_w, D_, 0, 0,
                      out, D_, 0, 0, 1, 1, 1.f, wo_b);
}

// round 2
// speedup vs baseline: 3.0839x; 3.0839x over previous
#include <cuda_runtime.h>
#include <math.h>
#include <stdint.h>

#define B_    2
#define S_    2048
#define D_    2048
#define H_    16
#define NT    4096          // B_*S_
#define QL    1024
#define KVL   512
#define NOPE_ 128
#define ROPE_ 64
#define VH_   128
#define QK_   192
#define KFW   576           // KVL + ROPE
#define HQK   3072          // H_*QK_
#define HQF   9216          // H_*KFW
#define SCALE 0.07216878364870322f   // 192^-0.5

// ---------------- scratch (static device globals; no runtime alloc) -------
__device__ float g_qa[(size_t)NT * QL];
__device__ float g_q [(size_t)NT * HQK];
__device__ float g_kvfull[(size_t)NT * KFW];
__device__ float g_qf[(size_t)NT * HQF];
__device__ float g_kf[(size_t)NT * KFW];
__device__ float g_scores[(size_t)B_ * H_ * S_ * S_];
__device__ float g_omid[(size_t)NT * H_ * KVL];
__device__ float g_ocat[(size_t)NT * H_ * VH_];

// ---------------- helpers ---------------------------------------------------
__device__ __forceinline__ uint32_t f2tf32(float f) {
    uint32_t r;
    asm("cvt.rna.tf32.f32 %0, %1;" : "=r"(r) : "f"(f));
    return r;
}

__device__ __forceinline__ void mma_tf32(float* c, const uint32_t* a, const uint32_t* b) {
    asm volatile(
        "mma.sync.aligned.m16n8k8.row.col.f32.tf32.tf32.f32 "
        "{%0,%1,%2,%3},{%4,%5,%6,%7},{%8,%9},{%0,%1,%2,%3};"
        : "+f"(c[0]), "+f"(c[1]), "+f"(c[2]), "+f"(c[3])
        : "r"(a[0]), "r"(a[1]), "r"(a[2]), "r"(a[3]), "r"(b[0]), "r"(b[1]));
}

// ---------------- TF32 tensor-core batched GEMM -----------------------------
// C[z] = alpha * A[z] @ op(B[z]) + bias
// TB=true : B is [N,K] row-major (op = B^T); TB=false: B is [K,N] row-major.
// TM=128 fixed; TN = 128 or 64. 256 threads.
template<int TN, bool TB>
__global__ void __launch_bounds__(256) gemm_tc(
    int M, int N, int K,
    const float* __restrict__ A, int lda, long long sAb, long long sAh,
    const float* __restrict__ Bp, int ldb, long long sBb, long long sBh,
    float* __restrict__ C, int ldc, long long sCb, long long sCh,
    int ZH, float alpha, const float* __restrict__ bias)
{
    constexpr int TM = 128, BK = 32;
    constexpr int WROWS = (TN == 128) ? 2 : 4;
    constexpr int WCOLS = 8 / WROWS;
    constexpr int WM = TM / WROWS;     // 64 or 32
    constexpr int WN = TN / WCOLS;     // 32
    constexpr int MT = WM / 16;        // 4 or 2
    constexpr int NT4 = WN / 8;        // 4
    constexpr int ASTR = BK + 4;       // 36  (stride ≡ 4 mod 32 -> conflict-free frag loads)
    constexpr int BSTR = TN + 8;       // 136/72 (stride ≡ 8 mod 32 -> conflict-free)
    constexpr int BITER = TN / 32;     // f4 loads per thread for B

    __shared__ __align__(16) uint32_t As[TM][ASTR];
    __shared__ __align__(16) uint32_t Bs[BK][BSTR];

    int z  = blockIdx.z;
    int zb = z / ZH;
    int zh = z - zb * ZH;
    const float* Ab = A  + zb * sAb + zh * sAh;
    const float* Bb = Bp + zb * sBb + zh * sBh;
    float*       Cb = C  + zb * sCb + zh * sCh;

    int row0 = blockIdx.y * TM;
    int col0 = blockIdx.x * TN;
    int tid  = threadIdx.x;
    int wid  = tid >> 5;
    int lane = tid & 31;
    int wr = wid / WCOLS, wc = wid % WCOLS;
    int wm0 = wr * WM, wn0 = wc * WN;
    int g = lane >> 2, t4 = lane & 3;

    float acc[MT][NT4][4] = {};

    for (int k0 = 0; k0 < K; k0 += BK) {
        // ---- global loads into registers ----
        float4 av[4];
        #pragma unroll
        for (int i = 0; i < 4; i++) {
            int idx = tid + 256 * i;
            int am = idx >> 3, akq = idx & 7;
            av[i] = *(const float4*)(Ab + (size_t)(row0 + am) * lda + k0 + akq * 4);
        }
        float4 bv[BITER];
        #pragma unroll
        for (int i = 0; i < BITER; i++) {
            int idx = tid + 256 * i;
            if (TB) {
                int bn = idx >> 3, bkq = idx & 7;
                bv[i] = *(const float4*)(Bb + (size_t)(col0 + bn) * ldb + k0 + bkq * 4);
            } else {
                int bk = idx / (TN / 4), bnq = idx % (TN / 4);
                bv[i] = *(const float4*)(Bb + (size_t)(k0 + bk) * ldb + col0 + bnq * 4);
            }
        }

        __syncthreads();

        // ---- store to shared with tf32 conversion ----
        #pragma unroll
        for (int i = 0; i < 4; i++) {
            int idx = tid + 256 * i;
            int am = idx >> 3, akq = idx & 7;
            As[am][akq * 4 + 0] = f2tf32(av[i].x);
            As[am][akq * 4 + 1] = f2tf32(av[i].y);
            As[am][akq * 4 + 2] = f2tf32(av[i].z);
            As[am][akq * 4 + 3] = f2tf32(av[i].w);
        }
        #pragma unroll
        for (int i = 0; i < BITER; i++) {
            int idx = tid + 256 * i;
            if (TB) {
                int bn = idx >> 3, bkq = idx & 7;
                Bs[bkq * 4 + 0][bn] = f2tf32(bv[i].x);
                Bs[bkq * 4 + 1][bn] = f2tf32(bv[i].y);
                Bs[bkq * 4 + 2][bn] = f2tf32(bv[i].z);
                Bs[bkq * 4 + 3][bn] = f2tf32(bv[i].w);
            } else {
                int bk = idx / (TN / 4), bnq = idx % (TN / 4);
                Bs[bk][bnq * 4 + 0] = f2tf32(bv[i].x);
                Bs[bk][bnq * 4 + 1] = f2tf32(bv[i].y);
                Bs[bk][bnq * 4 + 2] = f2tf32(bv[i].z);
                Bs[bk][bnq * 4 + 3] = f2tf32(bv[i].w);
            }
        }

        __syncthreads();

        // ---- tensor-core compute over 4 k-steps of 8 ----
        #pragma unroll
        for (int kk = 0; kk < 4; kk++) {
            int k8 = kk * 8;
            uint32_t afr[MT][4], bfr[NT4][2];
            #pragma unroll
            for (int mt = 0; mt < MT; mt++) {
                int m_ = wm0 + mt * 16;
                afr[mt][0] = As[m_ + g][k8 + t4];
                afr[mt][1] = As[m_ + g + 8][k8 + t4];
                afr[mt][2] = As[m_ + g][k8 + t4 + 4];
                afr[mt][3] = As[m_ + g + 8][k8 + t4 + 4];
            }
            #pragma unroll
            for (int nt = 0; nt < NT4; nt++) {
                int n_ = wn0 + nt * 8 + g;
                bfr[nt][0] = Bs[k8 + t4][n_];
                bfr[nt][1] = Bs[k8 + t4 + 4][n_];
            }
            #pragma unroll
            for (int mt = 0; mt < MT; mt++)
                #pragma unroll
                for (int nt = 0; nt < NT4; nt++)
                    mma_tf32(acc[mt][nt], afr[mt], bfr[nt]);
        }
        __syncthreads();
    }

    // ---- epilogue ----
    #pragma unroll
    for (int mt = 0; mt < MT; mt++) {
        int r0 = row0 + wm0 + mt * 16 + g;
        #pragma unroll
        for (int nt = 0; nt < NT4; nt++) {
            int c0c = col0 + wn0 + nt * 8 + 2 * t4;
            float b0 = bias ? bias[c0c] : 0.f;
            float b1 = bias ? bias[c0c + 1] : 0.f;
            Cb[(size_t)r0 * ldc + c0c]           = alpha * acc[mt][nt][0] + b0;
            Cb[(size_t)r0 * ldc + c0c + 1]       = alpha * acc[mt][nt][1] + b1;
            Cb[(size_t)(r0 + 8) * ldc + c0c]     = alpha * acc[mt][nt][2] + b0;
            Cb[(size_t)(r0 + 8) * ldc + c0c + 1] = alpha * acc[mt][nt][3] + b1;
        }
    }
}

// ---------------- rmsnorm ---------------------------------------------------
__global__ void rmsnorm_k(const float* __restrict__ in, float* __restrict__ out,
                          const float* __restrict__ w, int width,
                          int inStride, int outStride)
{
    int row = blockIdx.x;
    const float* ip = in  + (size_t)row * inStride;
    float*       op = out + (size_t)row * outStride;
    float ss = 0.f;
    for (int i = threadIdx.x; i < width; i += 256) {
        float v = ip[i];
        ss += v * v;
    }
    __shared__ float sm[256];
    sm[threadIdx.x] = ss;
    __syncthreads();
    for (int s = 128; s > 0; s >>= 1) {
        if (threadIdx.x < s) sm[threadIdx.x] += sm[threadIdx.x + s];
        __syncthreads();
    }
    float r = rsqrtf(sm[0] / (float)width + 1e-3f);
    for (int i = threadIdx.x; i < width; i += 256)
        op[i] = w[i] * ip[i] * r;
}

// ---------------- rope -------------------------------------------------------
__global__ void rope_q_k(const float* __restrict__ q, float* __restrict__ qf,
                         const float* __restrict__ c, const float* __restrict__ s)
{
    int tok = blockIdx.x;
    int h = threadIdx.x >> 5;
    int j = threadIdx.x & 31;
    int pos = tok % S_;
    const float* src = q  + (size_t)tok * HQK + h * QK_ + NOPE_;
    float*       dst = qf + (size_t)tok * HQF + h * KFW + KVL;
    float xr = src[2 * j], xi = src[2 * j + 1];
    float cc = c[pos * 32 + j], sn = s[pos * 32 + j];
    dst[2 * j]     = xr * cc - xi * sn;
    dst[2 * j + 1] = xr * sn + xi * cc;
}

__global__ void rope_k_k(const float* __restrict__ kvf, float* __restrict__ kf,
                         const float* __restrict__ c, const float* __restrict__ s)
{
    int tok = blockIdx.x;
    int j = threadIdx.x;   // 0..31
    int pos = tok % S_;
    const float* src = kvf + (size_t)tok * KFW + KVL;
    float*       dst = kf  + (size_t)tok * KFW + KVL;
    float xr = src[2 * j], xi = src[2 * j + 1];
    float cc = c[pos * 32 + j], sn = s[pos * 32 + j];
    dst[2 * j]     = xr * cc - xi * sn;
    dst[2 * j + 1] = xr * sn + xi * cc;
}

// ---------------- softmax over rows of length S_ ----------------------------
__global__ void softmax_k(float* __restrict__ d)
{
    size_t row = blockIdx.x;
    float* p = d + row * (size_t)S_;
    int t = threadIdx.x;
    float v[8];
    float m = -INFINITY;
    #pragma unroll
    for (int i = 0; i < 8; i++) {
        v[i] = p[t + i * 256];
        m = fmaxf(m, v[i]);
    }
    __shared__ float sm[256];
    sm[t] = m;
    __syncthreads();
    for (int s = 128; s > 0; s >>= 1) {
        if (t < s) sm[t] = fmaxf(sm[t], sm[t + s]);
        __syncthreads();
    }
    m = sm[0];
    __syncthreads();
    float sum = 0.f;
    #pragma unroll
    for (int i = 0; i < 8; i++) {
        v[i] = __expf(v[i] - m);
        sum += v[i];
    }
    sm[t] = sum;
    __syncthreads();
    for (int s = 128; s > 0; s >>= 1) {
        if (t < s) sm[t] += sm[t + s];
        __syncthreads();
    }
    float inv = 1.f / sm[0];
    #pragma unroll
    for (int i = 0; i < 8; i++)
        p[t + i * 256] = v[i] * inv;
}

// ---------------- host glue --------------------------------------------------
template<int TN, bool TB>
static void launch_gemm(int M, int N, int K,
                        const float* A, int lda, long long sAb, long long sAh,
                        const float* Bp, int ldb, long long sBb, long long sBh,
                        float* C, int ldc, long long sCb, long long sCh,
                        int nb, int nh, float alpha, const float* bias)
{
    dim3 grid(N / TN, M / 128, nb * nh);
    gemm_tc<TN, TB><<<grid, 256>>>(M, N, K, A, lda, sAb, sAh, Bp, ldb, sBb, sBh,
                                   C, ldc, sCb, sCh, nh, alpha, bias);
}

extern "C" void kernel_launch(void* const* d_in, const int* in_sizes, int n_in,
                              void* d_out, int out_size)
{
    const float* x        = (const float*)d_in[0];
    const float* cosp     = (const float*)d_in[2];
    const float* sinp     = (const float*)d_in[3];
    const float* wq_a_w   = (const float*)d_in[4];
    const float* wq_a_b   = (const float*)d_in[5];
    const float* q_norm_w = (const float*)d_in[6];
    const float* wq_b_w   = (const float*)d_in[7];
    const float* wq_b_b   = (const float*)d_in[8];
    const float* wkv_a_w  = (const float*)d_in[9];
    const float* wkv_a_b  = (const float*)d_in[10];
    const float* kv_norm_w= (const float*)d_in[11];
    const float* wkv_b_w  = (const float*)d_in[12];
    const float* wo_w     = (const float*)d_in[13];
    const float* wo_b     = (const float*)d_in[14];
    float* out = (float*)d_out;

    float *qa, *q, *kvf, *qf, *kf, *sc, *om, *oc;
    cudaGetSymbolAddress((void**)&qa,  g_qa);
    cudaGetSymbolAddress((void**)&q,   g_q);
    cudaGetSymbolAddress((void**)&kvf, g_kvfull);
    cudaGetSymbolAddress((void**)&qf,  g_qf);
    cudaGetSymbolAddress((void**)&kf,  g_kf);
    cudaGetSymbolAddress((void**)&sc,  g_scores);
    cudaGetSymbolAddress((void**)&om,  g_omid);
    cudaGetSymbolAddress((void**)&oc,  g_ocat);

    // 1) q_a = x @ wq_a^T + b          [4096,1024] K=2048
    launch_gemm<128, true>(NT, QL, D_, x, D_, 0, 0, wq_a_w, D_, 0, 0,
                           qa, QL, 0, 0, 1, 1, 1.f, wq_a_b);
    // 2) rmsnorm(q_a) in place
    rmsnorm_k<<<NT, 256>>>(qa, qa, q_norm_w, QL, QL, QL);
    // 3) q = q_a_n @ wq_b^T + b        [4096,3072] K=1024
    launch_gemm<128, true>(NT, HQK, QL, qa, QL, 0, 0, wq_b_w, QL, 0, 0,
                           q, HQK, 0, 0, 1, 1, 1.f, wq_b_b);
    // 4) kv_full = x @ wkv_a^T + b     [4096,576] K=2048  (N=576 -> TN=64)
    launch_gemm<64, true>(NT, KFW, D_, x, D_, 0, 0, wkv_a_w, D_, 0, 0,
                          kvf, KFW, 0, 0, 1, 1, 1.f, wkv_a_b);
    // 5) kf[:, :512] = rmsnorm(kv_full[:, :512])
    rmsnorm_k<<<NT, 256>>>(kvf, kf, kv_norm_w, KVL, KFW, KFW);
    // 6) kf[:, 512:576] = rope(k_pe)
    rope_k_k<<<NT, 32>>>(kvf, kf, cosp, sinp);
    // 7) qf[:, h, 512:576] = rope(q_pe)
    rope_q_k<<<NT, 512>>>(q, qf, cosp, sinp);
    // 8) qf[:, h, :512] = q_nope_h @ wkv_b[h,:128,:]   (NN, batched over h) K=128
    launch_gemm<128, false>(NT, KVL, NOPE_,
                            q, HQK, 0, QK_,
                            wkv_b_w, KVL, 0, (long long)(NOPE_ + VH_) * KVL,
                            qf, HQF, 0, KFW,
                            1, H_, 1.f, nullptr);
    // 9) scores[b,h] = SCALE * qf[b,:,h,:] @ kf[b]^T   [2048,2048]x32 K=576
    launch_gemm<128, true>(S_, S_, KFW,
                           qf, HQF, (long long)S_ * HQF, KFW,
                           kf, KFW, (long long)S_ * KFW, 0,
                           sc, S_, (long long)H_ * S_ * S_, (long long)S_ * S_,
                           B_, H_, SCALE, nullptr);
    // 10) softmax rows
    softmax_k<<<B_ * H_ * S_, 256>>>(sc);
    // 11) o_mid[b,:,h,:] = probs[b,h] @ kv_c[b]        (NN) [2048,512]x32 K=2048
    launch_gemm<128, false>(S_, KVL, S_,
                            sc, S_, (long long)H_ * S_ * S_, (long long)S_ * S_,
                            kf, KFW, (long long)S_ * KFW, 0,
                            om, H_ * KVL, (long long)S_ * H_ * KVL, KVL,
                            B_, H_, 1.f, nullptr);
    // 12) o_cat[:, h*128:] = o_mid_h @ wkv_b[h,128:,:]^T  (NT, batched) K=512
    launch_gemm<128, true>(NT, VH_, KVL,
                           om, H_ * KVL, 0, KVL,
                           wkv_b_w + (size_t)NOPE_ * KVL, KVL, 0,
                           (long long)(NOPE_ + VH_) * KVL,
                           oc, H_ * VH_, 0, VH_,
                           1, H_, 1.f, nullptr);
    // 13) out = o_cat @ wo^T + b        [4096,2048] K=2048
    launch_gemm<128, true>(NT, D_, H_ * VH_, oc, H_ * VH_, 0, 0, wo_w, D_, 0, 0,
                           out, D_, 0, 0, 1, 1, 1.f, wo_b);
}

// round 3
// speedup vs baseline: 4.1395x; 1.3423x over previous
#include <cuda_runtime.h>
#include <math.h>
#include <stdint.h>

#define B_    2
#define S_    2048
#define D_    2048
#define H_    16
#define NT    4096          // B_*S_
#define QL    1024
#define KVL   512
#define NOPE_ 128
#define ROPE_ 64
#define VH_   128
#define QK_   192
#define KFW   576           // KVL + ROPE
#define HQK   3072          // H_*QK_
#define HQF   9216          // H_*KFW
#define SCALE 0.07216878364870322f   // 192^-0.5

// ---------------- scratch (static device globals; no runtime alloc) -------
__device__ float g_qa[(size_t)NT * QL];
__device__ float g_q [(size_t)NT * HQK];
__device__ float g_kvfull[(size_t)NT * KFW];
__device__ float g_qf[(size_t)NT * HQF];
__device__ float g_kf[(size_t)NT * KFW];
__device__ float g_scores[(size_t)B_ * H_ * S_ * S_];
__device__ float g_omid[(size_t)NT * H_ * KVL];
__device__ float g_ocat[(size_t)NT * H_ * VH_];

// ---------------- helpers ---------------------------------------------------
__device__ __forceinline__ uint32_t f2tf32(float f) {
    uint32_t r;
    asm("cvt.rna.tf32.f32 %0, %1;" : "=r"(r) : "f"(f));
    return r;
}

__device__ __forceinline__ void mma_tf32(float* c, const uint32_t* a, const uint32_t* b) {
    asm volatile(
        "mma.sync.aligned.m16n8k8.row.col.f32.tf32.tf32.f32 "
        "{%0,%1,%2,%3},{%4,%5,%6,%7},{%8,%9},{%0,%1,%2,%3};"
        : "+f"(c[0]), "+f"(c[1]), "+f"(c[2]), "+f"(c[3])
        : "r"(a[0]), "r"(a[1]), "r"(a[2]), "r"(a[3]), "r"(b[0]), "r"(b[1]));
}

__device__ __forceinline__ void cp_async16(float* smem, const float* gmem) {
    uint32_t s = (uint32_t)__cvta_generic_to_shared(smem);
    asm volatile("cp.async.cg.shared.global [%0], [%1], 16;" :: "r"(s), "l"(gmem));
}
__device__ __forceinline__ void cp_commit() {
    asm volatile("cp.async.commit_group;");
}
template<int N>
__device__ __forceinline__ void cp_wait() {
    asm volatile("cp.async.wait_group %0;" :: "n"(N));
}

// ---------------- TF32 tensor-core batched GEMM, cp.async 2-stage -----------
// C[z] = alpha * A[z] @ op(B[z]) + bias
// TB=true : B is [N,K] row-major (op = B^T); TB=false: B is [K,N] row-major.
template<int TN, bool TB>
__global__ void __launch_bounds__(256, 2) gemm_tc(
    int M, int N, int K,
    const float* __restrict__ A, int lda, long long sAb, long long sAh,
    const float* __restrict__ Bp, int ldb, long long sBb, long long sBh,
    float* __restrict__ C, int ldc, long long sCb, long long sCh,
    int ZH, float alpha, const float* __restrict__ bias)
{
    constexpr int TM = 128, BK = 32;
    constexpr int WROWS = (TN == 128) ? 2 : 4;
    constexpr int WCOLS = 8 / WROWS;
    constexpr int WM = TM / WROWS;       // 64 or 32
    constexpr int WN = TN / WCOLS;       // 32
    constexpr int MT = WM / 16;          // 4 or 2
    constexpr int NT4 = WN / 8;          // 4
    constexpr int ASTR = BK + 4;         // 36: (4g+t4)%32 unique -> conflict-free
    constexpr int BSTR_N = TN + 8;       // (8t4+g)%32 unique -> conflict-free
    constexpr int ASZ = TM * ASTR;
    constexpr int BSZ = TB ? TN * ASTR : BK * BSTR_N;
    constexpr int AITER = TM * (BK / 4) / 256;      // 4
    constexpr int BITER = TN * (BK / 4) / 256;      // 4 or 2

    extern __shared__ float smemf[];
    float* sA = smemf;                // [2][ASZ]
    float* sB = smemf + 2 * ASZ;      // [2][BSZ]

    int z  = blockIdx.z;
    int zb = z / ZH;
    int zh = z - zb * ZH;
    const float* Ab = A  + zb * sAb + zh * sAh;
    const float* Bb = Bp + zb * sBb + zh * sBh;
    float*       Cb = C  + zb * sCb + zh * sCh;

    int row0 = blockIdx.y * TM;
    int col0 = blockIdx.x * TN;
    int tid  = threadIdx.x;
    int wid  = tid >> 5;
    int lane = tid & 31;
    int wr = wid / WCOLS, wc = wid % WCOLS;
    int wm0 = wr * WM, wn0 = wc * WN;
    int g = lane >> 2, t4 = lane & 3;

    float acc[MT][NT4][4] = {};

    auto load_stage = [&](int st, int k0) {
        float* a_s = sA + st * ASZ;
        float* b_s = sB + st * BSZ;
        #pragma unroll
        for (int i = 0; i < AITER; i++) {
            int idx = tid + 256 * i;
            int am = idx >> 3, akq = idx & 7;
            cp_async16(a_s + am * ASTR + akq * 4,
                       Ab + (size_t)(row0 + am) * lda + k0 + akq * 4);
        }
        #pragma unroll
        for (int i = 0; i < BITER; i++) {
            int idx = tid + 256 * i;
            if (TB) {
                int bn = idx >> 3, bkq = idx & 7;
                cp_async16(b_s + bn * ASTR + bkq * 4,
                           Bb + (size_t)(col0 + bn) * ldb + k0 + bkq * 4);
            } else {
                int bk = idx / (TN / 4), bnq = idx % (TN / 4);
                cp_async16(b_s + bk * BSTR_N + bnq * 4,
                           Bb + (size_t)(k0 + bk) * ldb + col0 + bnq * 4);
            }
        }
    };

    int nk = K / BK;
    load_stage(0, 0);
    cp_commit();

    for (int i = 0; i < nk; i++) {
        if (i + 1 < nk) load_stage((i + 1) & 1, (i + 1) * BK);
        cp_commit();                 // real or empty group -> keeps count
        cp_wait<1>();                // stage i resident
        __syncthreads();

        int st = i & 1;
        const float* a_s = sA + st * ASZ;
        const float* b_s = sB + st * BSZ;

        #pragma unroll
        for (int kk = 0; kk < 4; kk++) {
            int k8 = kk * 8;
            uint32_t afr[MT][4], bfr[NT4][2];
            #pragma unroll
            for (int mt = 0; mt < MT; mt++) {
                int m_ = wm0 + mt * 16;
                afr[mt][0] = f2tf32(a_s[(m_ + g) * ASTR + k8 + t4]);
                afr[mt][1] = f2tf32(a_s[(m_ + g + 8) * ASTR + k8 + t4]);
                afr[mt][2] = f2tf32(a_s[(m_ + g) * ASTR + k8 + t4 + 4]);
                afr[mt][3] = f2tf32(a_s[(m_ + g + 8) * ASTR + k8 + t4 + 4]);
            }
            #pragma unroll
            for (int nt = 0; nt < NT4; nt++) {
                int n_ = wn0 + nt * 8 + g;
                if (TB) {
                    bfr[nt][0] = f2tf32(b_s[n_ * ASTR + k8 + t4]);
                    bfr[nt][1] = f2tf32(b_s[n_ * ASTR + k8 + t4 + 4]);
                } else {
                    bfr[nt][0] = f2tf32(b_s[(k8 + t4) * BSTR_N + n_]);
                    bfr[nt][1] = f2tf32(b_s[(k8 + t4 + 4) * BSTR_N + n_]);
                }
            }
            #pragma unroll
            for (int mt = 0; mt < MT; mt++)
                #pragma unroll
                for (int nt = 0; nt < NT4; nt++)
                    mma_tf32(acc[mt][nt], afr[mt], bfr[nt]);
        }
        __syncthreads();
    }

    // ---- epilogue (float2 stores) ----
    #pragma unroll
    for (int mt = 0; mt < MT; mt++) {
        int r0 = row0 + wm0 + mt * 16 + g;
        #pragma unroll
        for (int nt = 0; nt < NT4; nt++) {
            int c0c = col0 + wn0 + nt * 8 + 2 * t4;
            float b0 = bias ? bias[c0c] : 0.f;
            float b1 = bias ? bias[c0c + 1] : 0.f;
            float2 v0 = {alpha * acc[mt][nt][0] + b0, alpha * acc[mt][nt][1] + b1};
            float2 v1 = {alpha * acc[mt][nt][2] + b0, alpha * acc[mt][nt][3] + b1};
            *(float2*)&Cb[(size_t)r0 * ldc + c0c] = v0;
            *(float2*)&Cb[(size_t)(r0 + 8) * ldc + c0c] = v1;
        }
    }
}

// ---------------- rmsnorm ---------------------------------------------------
__global__ void rmsnorm_k(const float* __restrict__ in, float* __restrict__ out,
                          const float* __restrict__ w, int width,
                          int inStride, int outStride)
{
    int row = blockIdx.x;
    const float* ip = in  + (size_t)row * inStride;
    float*       op = out + (size_t)row * outStride;
    float ss = 0.f;
    for (int i = threadIdx.x; i < width; i += 256) {
        float v = ip[i];
        ss += v * v;
    }
    __shared__ float sm[256];
    sm[threadIdx.x] = ss;
    __syncthreads();
    for (int s = 128; s > 0; s >>= 1) {
        if (threadIdx.x < s) sm[threadIdx.x] += sm[threadIdx.x + s];
        __syncthreads();
    }
    float r = rsqrtf(sm[0] / (float)width + 1e-3f);
    for (int i = threadIdx.x; i < width; i += 256)
        op[i] = w[i] * ip[i] * r;
}

// ---------------- rope -------------------------------------------------------
__global__ void rope_q_k(const float* __restrict__ q, float* __restrict__ qf,
                         const float* __restrict__ c, const float* __restrict__ s)
{
    int tok = blockIdx.x;
    int h = threadIdx.x >> 5;
    int j = threadIdx.x & 31;
    int pos = tok % S_;
    const float* src = q  + (size_t)tok * HQK + h * QK_ + NOPE_;
    float*       dst = qf + (size_t)tok * HQF + h * KFW + KVL;
    float xr = src[2 * j], xi = src[2 * j + 1];
    float cc = c[pos * 32 + j], sn = s[pos * 32 + j];
    dst[2 * j]     = xr * cc - xi * sn;
    dst[2 * j + 1] = xr * sn + xi * cc;
}

__global__ void rope_k_k(const float* __restrict__ kvf, float* __restrict__ kf,
                         const float* __restrict__ c, const float* __restrict__ s)
{
    int tok = blockIdx.x;
    int j = threadIdx.x;   // 0..31
    int pos = tok % S_;
    const float* src = kvf + (size_t)tok * KFW + KVL;
    float*       dst = kf  + (size_t)tok * KFW + KVL;
    float xr = src[2 * j], xi = src[2 * j + 1];
    float cc = c[pos * 32 + j], sn = s[pos * 32 + j];
    dst[2 * j]     = xr * cc - xi * sn;
    dst[2 * j + 1] = xr * sn + xi * cc;
}

// ---------------- softmax over rows of length S_ ----------------------------
__global__ void softmax_k(float* __restrict__ d)
{
    size_t row = blockIdx.x;
    float* p = d + row * (size_t)S_;
    int t = threadIdx.x;
    float v[8];
    float m = -INFINITY;
    #pragma unroll
    for (int i = 0; i < 8; i++) {
        v[i] = p[t + i * 256];
        m = fmaxf(m, v[i]);
    }
    __shared__ float sm[256];
    sm[t] = m;
    __syncthreads();
    for (int s = 128; s > 0; s >>= 1) {
        if (t < s) sm[t] = fmaxf(sm[t], sm[t + s]);
        __syncthreads();
    }
    m = sm[0];
    __syncthreads();
    float sum = 0.f;
    #pragma unroll
    for (int i = 0; i < 8; i++) {
        v[i] = __expf(v[i] - m);
        sum += v[i];
    }
    sm[t] = sum;
    __syncthreads();
    for (int s = 128; s > 0; s >>= 1) {
        if (t < s) sm[t] += sm[t + s];
        __syncthreads();
    }
    float inv = 1.f / sm[0];
    #pragma unroll
    for (int i = 0; i < 8; i++)
        p[t + i * 256] = v[i] * inv;
}

// ---------------- host glue --------------------------------------------------
template<int TN, bool TB>
static void launch_gemm(int M, int N, int K,
                        const float* A, int lda, long long sAb, long long sAh,
                        const float* Bp, int ldb, long long sBb, long long sBh,
                        float* C, int ldc, long long sCb, long long sCh,
                        int nb, int nh, float alpha, const float* bias)
{
    constexpr int ASZ = 128 * 36;
    constexpr int BSZ = TB ? TN * 36 : 32 * (TN + 8);
    constexpr int SMEM = (2 * ASZ + 2 * BSZ) * 4;
    cudaFuncSetAttribute(gemm_tc<TN, TB>,
                         cudaFuncAttributeMaxDynamicSharedMemorySize, SMEM);
    dim3 grid(N / TN, M / 128, nb * nh);
    gemm_tc<TN, TB><<<grid, 256, SMEM>>>(M, N, K, A, lda, sAb, sAh,
                                         Bp, ldb, sBb, sBh,
                                         C, ldc, sCb, sCh, nh, alpha, bias);
}

extern "C" void kernel_launch(void* const* d_in, const int* in_sizes, int n_in,
                              void* d_out, int out_size)
{
    const float* x        = (const float*)d_in[0];
    const float* cosp     = (const float*)d_in[2];
    const float* sinp     = (const float*)d_in[3];
    const float* wq_a_w   = (const float*)d_in[4];
    const float* wq_a_b   = (const float*)d_in[5];
    const float* q_norm_w = (const float*)d_in[6];
    const float* wq_b_w   = (const float*)d_in[7];
    const float* wq_b_b   = (const float*)d_in[8];
    const float* wkv_a_w  = (const float*)d_in[9];
    const float* wkv_a_b  = (const float*)d_in[10];
    const float* kv_norm_w= (const float*)d_in[11];
    const float* wkv_b_w  = (const float*)d_in[12];
    const float* wo_w     = (const float*)d_in[13];
    const float* wo_b     = (const float*)d_in[14];
    float* out = (float*)d_out;

    float *qa, *q, *kvf, *qf, *kf, *sc, *om, *oc;
    cudaGetSymbolAddress((void**)&qa,  g_qa);
    cudaGetSymbolAddress((void**)&q,   g_q);
    cudaGetSymbolAddress((void**)&kvf, g_kvfull);
    cudaGetSymbolAddress((void**)&qf,  g_qf);
    cudaGetSymbolAddress((void**)&kf,  g_kf);
    cudaGetSymbolAddress((void**)&sc,  g_scores);
    cudaGetSymbolAddress((void**)&om,  g_omid);
    cudaGetSymbolAddress((void**)&oc,  g_ocat);

    // 1) q_a = x @ wq_a^T + b          [4096,1024] K=2048
    launch_gemm<128, true>(NT, QL, D_, x, D_, 0, 0, wq_a_w, D_, 0, 0,
                           qa, QL, 0, 0, 1, 1, 1.f, wq_a_b);
    // 2) rmsnorm(q_a) in place
    rmsnorm_k<<<NT, 256>>>(qa, qa, q_norm_w, QL, QL, QL);
    // 3) q = q_a_n @ wq_b^T + b        [4096,3072] K=1024
    launch_gemm<128, true>(NT, HQK, QL, qa, QL, 0, 0, wq_b_w, QL, 0, 0,
                           q, HQK, 0, 0, 1, 1, 1.f, wq_b_b);
    // 4) kv_full = x @ wkv_a^T + b     [4096,576] K=2048
    launch_gemm<64, true>(NT, KFW, D_, x, D_, 0, 0, wkv_a_w, D_, 0, 0,
                          kvf, KFW, 0, 0, 1, 1, 1.f, wkv_a_b);
    // 5) kf[:, :512] = rmsnorm(kv_full[:, :512])
    rmsnorm_k<<<NT, 256>>>(kvf, kf, kv_norm_w, KVL, KFW, KFW);
    // 6) kf[:, 512:576] = rope(k_pe)
    rope_k_k<<<NT, 32>>>(kvf, kf, cosp, sinp);
    // 7) qf[:, h, 512:576] = rope(q_pe)
    rope_q_k<<<NT, 512>>>(q, qf, cosp, sinp);
    // 8) qf[:, h, :512] = q_nope_h @ wkv_b[h,:128,:]   (NN, batched) K=128
    launch_gemm<128, false>(NT, KVL, NOPE_,
                            q, HQK, 0, QK_,
                            wkv_b_w, KVL, 0, (long long)(NOPE_ + VH_) * KVL,
                            qf, HQF, 0, KFW,
                            1, H_, 1.f, nullptr);
    // 9) scores[b,h] = SCALE * qf[b,:,h,:] @ kf[b]^T   [2048,2048]x32 K=576
    launch_gemm<128, true>(S_, S_, KFW,
                           qf, HQF, (long long)S_ * HQF, KFW,
                           kf, KFW, (long long)S_ * KFW, 0,
                           sc, S_, (long long)H_ * S_ * S_, (long long)S_ * S_,
                           B_, H_, SCALE, nullptr);
    // 10) softmax rows
    softmax_k<<<B_ * H_ * S_, 256>>>(sc);
    // 11) o_mid[b,:,h,:] = probs[b,h] @ kv_c[b]        (NN) [2048,512]x32 K=2048
    launch_gemm<128, false>(S_, KVL, S_,
                            sc, S_, (long long)H_ * S_ * S_, (long long)S_ * S_,
                            kf, KFW, (long long)S_ * KFW, 0,
                            om, H_ * KVL, (long long)S_ * H_ * KVL, KVL,
                            B_, H_, 1.f, nullptr);
    // 12) o_cat[:, h*128:] = o_mid_h @ wkv_b[h,128:,:]^T  (NT, batched) K=512
    launch_gemm<128, true>(NT, VH_, KVL,
                           om, H_ * KVL, 0, KVL,
                           wkv_b_w + (size_t)NOPE_ * KVL, KVL, 0,
                           (long long)(NOPE_ + VH_) * KVL,
                           oc, H_ * VH_, 0, VH_,
                           1, H_, 1.f, nullptr);
    // 13) out = o_cat @ wo^T + b        [4096,2048] K=2048
    launch_gemm<128, true>(NT, D_, H_ * VH_, oc, H_ * VH_, 0, 0, wo_w, D_, 0, 0,
                           out, D_, 0, 0, 1, 1, 1.f, wo_b);
}

// round 4
// speedup vs baseline: 4.2650x; 1.0303x over previous
#include <cuda_runtime.h>
#include <math.h>
#include <stdint.h>

#define B_    2
#define S_    2048
#define D_    2048
#define H_    16
#define NT    4096          // B_*S_
#define QL    1024
#define KVL   512
#define NOPE_ 128
#define ROPE_ 64
#define VH_   128
#define QK_   192
#define KFW   576           // KVL + ROPE
#define HQK   3072          // H_*QK_
#define HQF   9216          // H_*KFW
#define SCALE 0.07216878364870322f   // 192^-0.5

// ---------------- scratch (static device globals; no runtime alloc) -------
__device__ float g_qa[(size_t)NT * QL];
__device__ float g_q [(size_t)NT * HQK];
__device__ float g_kvfull[(size_t)NT * KFW];
__device__ float g_qf[(size_t)NT * HQF];
__device__ float g_kf[(size_t)NT * KFW];
__device__ float g_scores[(size_t)B_ * H_ * S_ * S_];
__device__ float g_omid[(size_t)NT * H_ * KVL];
__device__ float g_ocat[(size_t)NT * H_ * VH_];
// tf32-rounded copies of inputs
__device__ float g_xr   [(size_t)NT * D_];
__device__ float g_wqa_r[(size_t)QL * D_];
__device__ float g_wqb_r[(size_t)HQK * QL];
__device__ float g_wkva_r[(size_t)KFW * D_];
__device__ float g_wkvb_r[(size_t)H_ * (NOPE_ + VH_) * KVL];
__device__ float g_wo_r [(size_t)D_ * H_ * VH_];

// ---------------- helpers ---------------------------------------------------
__device__ __forceinline__ uint32_t f2tf32(float f) {
    uint32_t r;
    asm("cvt.rna.tf32.f32 %0, %1;" : "=r"(r) : "f"(f));
    return r;
}
__device__ __forceinline__ float rnd_tf32(float f) {
    return __uint_as_float(f2tf32(f));
}

__device__ __forceinline__ void mma_tf32(float* c, const uint32_t* a, const uint32_t* b) {
    asm volatile(
        "mma.sync.aligned.m16n8k8.row.col.f32.tf32.tf32.f32 "
        "{%0,%1,%2,%3},{%4,%5,%6,%7},{%8,%9},{%0,%1,%2,%3};"
        : "+f"(c[0]), "+f"(c[1]), "+f"(c[2]), "+f"(c[3])
        : "r"(a[0]), "r"(a[1]), "r"(a[2]), "r"(a[3]), "r"(b[0]), "r"(b[1]));
}

__device__ __forceinline__ void cp_async16(float* smem, const float* gmem) {
    uint32_t s = (uint32_t)__cvta_generic_to_shared(smem);
    asm volatile("cp.async.cg.shared.global [%0], [%1], 16;" :: "r"(s), "l"(gmem));
}
__device__ __forceinline__ void cp_commit() {
    asm volatile("cp.async.commit_group;");
}
template<int N>
__device__ __forceinline__ void cp_wait() {
    asm volatile("cp.async.wait_group %0;" :: "n"(N));
}

// ---------------- tf32 rounding copy (elementwise) ---------------------------
__global__ void round_copy_k(const float* __restrict__ in, float* __restrict__ out)
{
    size_t i = ((size_t)blockIdx.x * 256 + threadIdx.x) * 4;
    float4 v = *(const float4*)(in + i);
    v.x = rnd_tf32(v.x); v.y = rnd_tf32(v.y);
    v.z = rnd_tf32(v.z); v.w = rnd_tf32(v.w);
    *(float4*)(out + i) = v;
}

// ---------------- TF32 tensor-core batched GEMM, cp.async 2-stage -----------
// Inputs MUST be tf32-pre-rounded. C[z] = alpha * A[z] @ op(B[z]) + bias.
// TB=true : B is [N,K] row-major (op = B^T); TB=false: B is [K,N] row-major.
// RND: round outputs to tf32 (for outputs feeding another GEMM directly).
template<int TN, bool TB, bool RND>
__global__ void __launch_bounds__(256, 2) gemm_tc(
    int M, int N, int K,
    const float* __restrict__ A, int lda, long long sAb, long long sAh,
    const float* __restrict__ Bp, int ldb, long long sBb, long long sBh,
    float* __restrict__ C, int ldc, long long sCb, long long sCh,
    int ZH, float alpha, const float* __restrict__ bias)
{
    constexpr int TM = 128, BK = 32;
    constexpr int WROWS = (TN == 128) ? 2 : 4;
    constexpr int WCOLS = 8 / WROWS;
    constexpr int WM = TM / WROWS;       // 64 or 32
    constexpr int WN = TN / WCOLS;       // 32
    constexpr int MT = WM / 16;          // 4 or 2
    constexpr int NT4 = WN / 8;          // 4
    constexpr int ASTR = BK + 4;         // 36: conflict-free frag loads
    constexpr int BSTR_N = TN + 8;
    constexpr int ASZ = TM * ASTR;
    constexpr int BSZ = TB ? TN * ASTR : BK * BSTR_N;
    constexpr int AITER = TM * (BK / 4) / 256;
    constexpr int BITER = TN * (BK / 4) / 256;

    extern __shared__ float smemf[];
    float* sA = smemf;                // [2][ASZ]
    float* sB = smemf + 2 * ASZ;      // [2][BSZ]

    int z  = blockIdx.z;
    int zb = z / ZH;
    int zh = z - zb * ZH;
    const float* Ab = A  + zb * sAb + zh * sAh;
    const float* Bb = Bp + zb * sBb + zh * sBh;
    float*       Cb = C  + zb * sCb + zh * sCh;

    int row0 = blockIdx.y * TM;
    int col0 = blockIdx.x * TN;
    int tid  = threadIdx.x;
    int wid  = tid >> 5;
    int lane = tid & 31;
    int wr = wid / WCOLS, wc = wid % WCOLS;
    int wm0 = wr * WM, wn0 = wc * WN;
    int g = lane >> 2, t4 = lane & 3;

    float acc[MT][NT4][4] = {};

    auto load_stage = [&](int st, int k0) {
        float* a_s = sA + st * ASZ;
        float* b_s = sB + st * BSZ;
        #pragma unroll
        for (int i = 0; i < AITER; i++) {
            int idx = tid + 256 * i;
            int am = idx >> 3, akq = idx & 7;
            cp_async16(a_s + am * ASTR + akq * 4,
                       Ab + (size_t)(row0 + am) * lda + k0 + akq * 4);
        }
        #pragma unroll
        for (int i = 0; i < BITER; i++) {
            int idx = tid + 256 * i;
            if (TB) {
                int bn = idx >> 3, bkq = idx & 7;
                cp_async16(b_s + bn * ASTR + bkq * 4,
                           Bb + (size_t)(col0 + bn) * ldb + k0 + bkq * 4);
            } else {
                int bk = idx / (TN / 4), bnq = idx % (TN / 4);
                cp_async16(b_s + bk * BSTR_N + bnq * 4,
                           Bb + (size_t)(k0 + bk) * ldb + col0 + bnq * 4);
            }
        }
    };

    int nk = K / BK;
    load_stage(0, 0);
    cp_commit();

    for (int i = 0; i < nk; i++) {
        if (i + 1 < nk) load_stage((i + 1) & 1, (i + 1) * BK);
        cp_commit();
        cp_wait<1>();
        __syncthreads();

        int st = i & 1;
        const uint32_t* a_s = (const uint32_t*)(sA + st * ASZ);
        const uint32_t* b_s = (const uint32_t*)(sB + st * BSZ);

        #pragma unroll
        for (int kk = 0; kk < 4; kk++) {
            int k8 = kk * 8;
            uint32_t afr[MT][4], bfr[NT4][2];
            #pragma unroll
            for (int mt = 0; mt < MT; mt++) {
                int m_ = wm0 + mt * 16;
                afr[mt][0] = a_s[(m_ + g) * ASTR + k8 + t4];
                afr[mt][1] = a_s[(m_ + g + 8) * ASTR + k8 + t4];
                afr[mt][2] = a_s[(m_ + g) * ASTR + k8 + t4 + 4];
                afr[mt][3] = a_s[(m_ + g + 8) * ASTR + k8 + t4 + 4];
            }
            #pragma unroll
            for (int nt = 0; nt < NT4; nt++) {
                int n_ = wn0 + nt * 8 + g;
                if (TB) {
                    bfr[nt][0] = b_s[n_ * ASTR + k8 + t4];
                    bfr[nt][1] = b_s[n_ * ASTR + k8 + t4 + 4];
                } else {
                    bfr[nt][0] = b_s[(k8 + t4) * BSTR_N + n_];
                    bfr[nt][1] = b_s[(k8 + t4 + 4) * BSTR_N + n_];
                }
            }
            #pragma unroll
            for (int mt = 0; mt < MT; mt++)
                #pragma unroll
                for (int nt = 0; nt < NT4; nt++)
                    mma_tf32(acc[mt][nt], afr[mt], bfr[nt]);
        }
        __syncthreads();
    }

    // ---- epilogue ----
    #pragma unroll
    for (int mt = 0; mt < MT; mt++) {
        int r0 = row0 + wm0 + mt * 16 + g;
        #pragma unroll
        for (int nt = 0; nt < NT4; nt++) {
            int c0c = col0 + wn0 + nt * 8 + 2 * t4;
            float b0 = bias ? bias[c0c] : 0.f;
            float b1 = bias ? bias[c0c + 1] : 0.f;
            float v00 = alpha * acc[mt][nt][0] + b0;
            float v01 = alpha * acc[mt][nt][1] + b1;
            float v10 = alpha * acc[mt][nt][2] + b0;
            float v11 = alpha * acc[mt][nt][3] + b1;
            if (RND) {
                v00 = rnd_tf32(v00); v01 = rnd_tf32(v01);
                v10 = rnd_tf32(v10); v11 = rnd_tf32(v11);
            }
            *(float2*)&Cb[(size_t)r0 * ldc + c0c]       = make_float2(v00, v01);
            *(float2*)&Cb[(size_t)(r0 + 8) * ldc + c0c] = make_float2(v10, v11);
        }
    }
}

// ---------------- rmsnorm (tf32-rounded output) ------------------------------
__global__ void rmsnorm_k(const float* __restrict__ in, float* __restrict__ out,
                          const float* __restrict__ w, int width,
                          int inStride, int outStride)
{
    int row = blockIdx.x;
    const float* ip = in  + (size_t)row * inStride;
    float*       op = out + (size_t)row * outStride;
    float ss = 0.f;
    for (int i = threadIdx.x; i < width; i += 256) {
        float v = ip[i];
        ss += v * v;
    }
    __shared__ float sm[256];
    sm[threadIdx.x] = ss;
    __syncthreads();
    for (int s = 128; s > 0; s >>= 1) {
        if (threadIdx.x < s) sm[threadIdx.x] += sm[threadIdx.x + s];
        __syncthreads();
    }
    float r = rsqrtf(sm[0] / (float)width + 1e-3f);
    for (int i = threadIdx.x; i < width; i += 256)
        op[i] = rnd_tf32(w[i] * ip[i] * r);
}

// ---------------- rope (tf32-rounded output) ---------------------------------
__global__ void rope_q_k(const float* __restrict__ q, float* __restrict__ qf,
                         const float* __restrict__ c, const float* __restrict__ s)
{
    int tok = blockIdx.x;
    int h = threadIdx.x >> 5;
    int j = threadIdx.x & 31;
    int pos = tok % S_;
    const float* src = q  + (size_t)tok * HQK + h * QK_ + NOPE_;
    float*       dst = qf + (size_t)tok * HQF + h * KFW + KVL;
    float xr = src[2 * j], xi = src[2 * j + 1];
    float cc = c[pos * 32 + j], sn = s[pos * 32 + j];
    dst[2 * j]     = rnd_tf32(xr * cc - xi * sn);
    dst[2 * j + 1] = rnd_tf32(xr * sn + xi * cc);
}

__global__ void rope_k_k(const float* __restrict__ kvf, float* __restrict__ kf,
                         const float* __restrict__ c, const float* __restrict__ s)
{
    int tok = blockIdx.x;
    int j = threadIdx.x;   // 0..31
    int pos = tok % S_;
    const float* src = kvf + (size_t)tok * KFW + KVL;
    float*       dst = kf  + (size_t)tok * KFW + KVL;
    float xr = src[2 * j], xi = src[2 * j + 1];
    float cc = c[pos * 32 + j], sn = s[pos * 32 + j];
    dst[2 * j]     = rnd_tf32(xr * cc - xi * sn);
    dst[2 * j + 1] = rnd_tf32(xr * sn + xi * cc);
}

// ---------------- softmax (tf32-rounded output) -------------------------------
__global__ void softmax_k(float* __restrict__ d)
{
    size_t row = blockIdx.x;
    float* p = d + row * (size_t)S_;
    int t = threadIdx.x;
    float v[8];
    float m = -INFINITY;
    #pragma unroll
    for (int i = 0; i < 8; i++) {
        v[i] = p[t + i * 256];
        m = fmaxf(m, v[i]);
    }
    __shared__ float sm[256];
    sm[t] = m;
    __syncthreads();
    for (int s = 128; s > 0; s >>= 1) {
        if (t < s) sm[t] = fmaxf(sm[t], sm[t + s]);
        __syncthreads();
    }
    m = sm[0];
    __syncthreads();
    float sum = 0.f;
    #pragma unroll
    for (int i = 0; i < 8; i++) {
        v[i] = __expf(v[i] - m);
        sum += v[i];
    }
    sm[t] = sum;
    __syncthreads();
    for (int s = 128; s > 0; s >>= 1) {
        if (t < s) sm[t] += sm[t + s];
        __syncthreads();
    }
    float inv = 1.f / sm[0];
    #pragma unroll
    for (int i = 0; i < 8; i++)
        p[t + i * 256] = rnd_tf32(v[i] * inv);
}

// ---------------- host glue --------------------------------------------------
template<int TN, bool TB, bool RND>
static void launch_gemm(int M, int N, int K,
                        const float* A, int lda, long long sAb, long long sAh,
                        const float* Bp, int ldb, long long sBb, long long sBh,
                        float* C, int ldc, long long sCb, long long sCh,
                        int nb, int nh, float alpha, const float* bias)
{
    constexpr int ASZ = 128 * 36;
    constexpr int BSZ = TB ? TN * 36 : 32 * (TN + 8);
    constexpr int SMEM = (2 * ASZ + 2 * BSZ) * 4;
    cudaFuncSetAttribute(gemm_tc<TN, TB, RND>,
                         cudaFuncAttributeMaxDynamicSharedMemorySize, SMEM);
    dim3 grid(N / TN, M / 128, nb * nh);
    gemm_tc<TN, TB, RND><<<grid, 256, SMEM>>>(M, N, K, A, lda, sAb, sAh,
                                              Bp, ldb, sBb, sBh,
                                              C, ldc, sCb, sCh, nh, alpha, bias);
}

static void round_copy(const float* in, float* out, size_t n)
{
    round_copy_k<<<(unsigned)(n / 1024), 256>>>(in, out);
}

extern "C" void kernel_launch(void* const* d_in, const int* in_sizes, int n_in,
                              void* d_out, int out_size)
{
    const float* x        = (const float*)d_in[0];
    const float* cosp     = (const float*)d_in[2];
    const float* sinp     = (const float*)d_in[3];
    const float* wq_a_w   = (const float*)d_in[4];
    const float* wq_a_b   = (const float*)d_in[5];
    const float* q_norm_w = (const float*)d_in[6];
    const float* wq_b_w   = (const float*)d_in[7];
    const float* wq_b_b   = (const float*)d_in[8];
    const float* wkv_a_w  = (const float*)d_in[9];
    const float* wkv_a_b  = (const float*)d_in[10];
    const float* kv_norm_w= (const float*)d_in[11];
    const float* wkv_b_w  = (const float*)d_in[12];
    const float* wo_w     = (const float*)d_in[13];
    const float* wo_b     = (const float*)d_in[14];
    float* out = (float*)d_out;

    float *qa, *q, *kvf, *qf, *kf, *sc, *om, *oc;
    float *xr, *wqa, *wqb, *wkva, *wkvb, *wo;
    cudaGetSymbolAddress((void**)&qa,  g_qa);
    cudaGetSymbolAddress((void**)&q,   g_q);
    cudaGetSymbolAddress((void**)&kvf, g_kvfull);
    cudaGetSymbolAddress((void**)&qf,  g_qf);
    cudaGetSymbolAddress((void**)&kf,  g_kf);
    cudaGetSymbolAddress((void**)&sc,  g_scores);
    cudaGetSymbolAddress((void**)&om,  g_omid);
    cudaGetSymbolAddress((void**)&oc,  g_ocat);
    cudaGetSymbolAddress((void**)&xr,  g_xr);
    cudaGetSymbolAddress((void**)&wqa, g_wqa_r);
    cudaGetSymbolAddress((void**)&wqb, g_wqb_r);
    cudaGetSymbolAddress((void**)&wkva,g_wkva_r);
    cudaGetSymbolAddress((void**)&wkvb,g_wkvb_r);
    cudaGetSymbolAddress((void**)&wo,  g_wo_r);

    // 0) tf32-round inputs once
    round_copy(x,       xr,   (size_t)NT * D_);
    round_copy(wq_a_w,  wqa,  (size_t)QL * D_);
    round_copy(wq_b_w,  wqb,  (size_t)HQK * QL);
    round_copy(wkv_a_w, wkva, (size_t)KFW * D_);
    round_copy(wkv_b_w, wkvb, (size_t)H_ * (NOPE_ + VH_) * KVL);
    round_copy(wo_w,    wo,   (size_t)D_ * H_ * VH_);

    // 1) q_a = x @ wq_a^T + b          [4096,1024] K=2048 (rmsnorm rounds)
    launch_gemm<128, true, false>(NT, QL, D_, xr, D_, 0, 0, wqa, D_, 0, 0,
                                  qa, QL, 0, 0, 1, 1, 1.f, wq_a_b);
    // 2) rmsnorm(q_a) in place (rounded)
    rmsnorm_k<<<NT, 256>>>(qa, qa, q_norm_w, QL, QL, QL);
    // 3) q = q_a_n @ wq_b^T + b        [4096,3072] K=1024 (rounded: feeds GEMM 8)
    launch_gemm<128, true, true>(NT, HQK, QL, qa, QL, 0, 0, wqb, QL, 0, 0,
                                 q, HQK, 0, 0, 1, 1, 1.f, wq_b_b);
    // 4) kv_full = x @ wkv_a^T + b     [4096,576] K=2048 (rmsnorm/rope round)
    launch_gemm<64, true, false>(NT, KFW, D_, xr, D_, 0, 0, wkva, D_, 0, 0,
                                 kvf, KFW, 0, 0, 1, 1, 1.f, wkv_a_b);
    // 5) kf[:, :512] = rmsnorm(kv_full[:, :512]) (rounded)
    rmsnorm_k<<<NT, 256>>>(kvf, kf, kv_norm_w, KVL, KFW, KFW);
    // 6) kf[:, 512:576] = rope(k_pe) (rounded)
    rope_k_k<<<NT, 32>>>(kvf, kf, cosp, sinp);
    // 7) qf[:, h, 512:576] = rope(q_pe) (rounded)
    rope_q_k<<<NT, 512>>>(q, qf, cosp, sinp);
    // 8) qf[:, h, :512] = q_nope_h @ wkv_b[h,:128,:] (rounded: feeds GEMM 9)
    launch_gemm<128, false, true>(NT, KVL, NOPE_,
                                  q, HQK, 0, QK_,
                                  wkvb, KVL, 0, (long long)(NOPE_ + VH_) * KVL,
                                  qf, HQF, 0, KFW,
                                  1, H_, 1.f, nullptr);
    // 9) scores = SCALE * qf @ kf^T    [2048,2048]x32 K=576 (softmax rounds)
    launch_gemm<128, true, false>(S_, S_, KFW,
                                  qf, HQF, (long long)S_ * HQF, KFW,
                                  kf, KFW, (long long)S_ * KFW, 0,
                                  sc, S_, (long long)H_ * S_ * S_, (long long)S_ * S_,
                                  B_, H_, SCALE, nullptr);
    // 10) softmax rows (rounded output)
    softmax_k<<<B_ * H_ * S_, 256>>>(sc);
    // 11) o_mid = probs @ kv_c         (NN) [2048,512]x32 (rounded: feeds GEMM 12)
    launch_gemm<128, false, true>(S_, KVL, S_,
                                  sc, S_, (long long)H_ * S_ * S_, (long long)S_ * S_,
                                  kf, KFW, (long long)S_ * KFW, 0,
                                  om, H_ * KVL, (long long)S_ * H_ * KVL, KVL,
                                  B_, H_, 1.f, nullptr);
    // 12) o_cat = o_mid @ wkv_b_v^T    (NT, batched) K=512 (rounded: feeds GEMM 13)
    launch_gemm<128, true, true>(NT, VH_, KVL,
                                 om, H_ * KVL, 0, KVL,
                                 wkvb + (size_t)NOPE_ * KVL, KVL, 0,
                                 (long long)(NOPE_ + VH_) * KVL,
                                 oc, H_ * VH_, 0, VH_,
                                 1, H_, 1.f, nullptr);
    // 13) out = o_cat @ wo^T + b       [4096,2048] K=2048 (final: fp32)
    launch_gemm<128, true, false>(NT, D_, H_ * VH_, oc, H_ * VH_, 0, 0, wo, D_, 0, 0,
                                  out, D_, 0, 0, 1, 1, 1.f, wo_b);
}

// round 6
// speedup vs baseline: 4.4131x; 1.0347x over previous
#include <cuda_runtime.h>
#include <math.h>
#include <stdint.h>

#define B_    2
#define S_    2048
#define D_    2048
#define H_    16
#define NT    4096          // B_*S_
#define QL    1024
#define KVL   512
#define NOPE_ 128
#define ROPE_ 64
#define VH_   128
#define QK_   192
#define KFW   576           // KVL + ROPE
#define HQK   3072          // H_*QK_
#define HQF   9216          // H_*KFW
#define SCALE 0.07216878364870322f   // 192^-0.5

// ---------------- scratch (static device globals; no runtime alloc) -------
__device__ float g_qa[(size_t)NT * QL];
__device__ float g_q [(size_t)NT * HQK];
__device__ float g_kvfull[(size_t)NT * KFW];
__device__ float g_qf[(size_t)NT * HQF];
__device__ float g_kf[(size_t)NT * KFW];
__device__ float g_scores[(size_t)B_ * H_ * S_ * S_];
__device__ float g_omid[(size_t)NT * H_ * KVL];
__device__ float g_ocat[(size_t)NT * H_ * VH_];
// tf32-rounded copies of inputs
__device__ float g_xr   [(size_t)NT * D_];
__device__ float g_wqa_r[(size_t)QL * D_];
__device__ float g_wqb_r[(size_t)HQK * QL];
__device__ float g_wkva_r[(size_t)KFW * D_];
__device__ float g_wkvb_r[(size_t)H_ * (NOPE_ + VH_) * KVL];
__device__ float g_wo_r [(size_t)D_ * H_ * VH_];

// ---------------- helpers ---------------------------------------------------
__device__ __forceinline__ uint32_t f2tf32(float f) {
    uint32_t r;
    asm("cvt.rna.tf32.f32 %0, %1;" : "=r"(r) : "f"(f));
    return r;
}
__device__ __forceinline__ float rnd_tf32(float f) {
    return __uint_as_float(f2tf32(f));
}

__device__ __forceinline__ void mma_tf32(float* c, const uint32_t* a, const uint32_t* b) {
    asm volatile(
        "mma.sync.aligned.m16n8k8.row.col.f32.tf32.tf32.f32 "
        "{%0,%1,%2,%3},{%4,%5,%6,%7},{%8,%9},{%0,%1,%2,%3};"
        : "+f"(c[0]), "+f"(c[1]), "+f"(c[2]), "+f"(c[3])
        : "r"(a[0]), "r"(a[1]), "r"(a[2]), "r"(a[3]), "r"(b[0]), "r"(b[1]));
}

__device__ __forceinline__ void cp_async16(float* smem, const float* gmem) {
    uint32_t s = (uint32_t)__cvta_generic_to_shared(smem);
    asm volatile("cp.async.cg.shared.global [%0], [%1], 16;" :: "r"(s), "l"(gmem));
}
__device__ __forceinline__ void cp_commit() {
    asm volatile("cp.async.commit_group;");
}
template<int N>
__device__ __forceinline__ void cp_wait() {
    asm volatile("cp.async.wait_group %0;" :: "n"(N));
}

// =============================================================================
// gemm_w64: 128x128 CTA tile, 128 threads (4 warps, 2x2), warp tile 64x64,
// BK=32, 3-stage cp.async pipeline, ONE __syncthreads per K-tile.
// C[z] = alpha * A[z] @ op(B[z]) + bias.  Inputs tf32-pre-rounded.
// TB=true: B [N,K] row-major; TB=false: B [K,N] row-major.
// =============================================================================
template<bool TB, bool RND>
__global__ void __launch_bounds__(128) gemm_w64(
    int K,
    const float* __restrict__ A, int lda, long long sAb, long long sAh,
    const float* __restrict__ Bp, int ldb, long long sBb, long long sBh,
    float* __restrict__ C, int ldc, long long sCb, long long sCh,
    int ZH, float alpha, const float* __restrict__ bias)
{
    constexpr int BK = 32;
    constexpr int ASTR = 36;                 // (g*36+t4)%32 unique -> conflict-free
    constexpr int BSTR_N = 136;              // (t4*136+g)%32 = 8t4+g unique
    constexpr int ASZ = 128 * ASTR;          // floats per A stage
    constexpr int BSZ = TB ? 128 * ASTR : BK * BSTR_N;

    extern __shared__ float smemf[];
    float* sA = smemf;                        // [3][ASZ]
    float* sB = smemf + 3 * ASZ;              // [3][BSZ]

    int z  = blockIdx.z;
    int zb = z / ZH;
    int zh = z - zb * ZH;
    const float* Ab = A  + zb * sAb + zh * sAh;
    const float* Bb = Bp + zb * sBb + zh * sBh;
    float*       Cb = C  + zb * sCb + zh * sCh;

    int row0 = blockIdx.y << 7;
    int col0 = blockIdx.x << 7;
    int tid  = threadIdx.x;
    int wid  = tid >> 5;
    int lane = tid & 31;
    int wm0 = (wid >> 1) << 6;               // 0 or 64
    int wn0 = (wid & 1) << 6;                // 0 or 64
    int g = lane >> 2, t4 = lane & 3;

    float acc[4][8][4] = {};

    auto load_stage = [&](int st, int k0) {
        float* a_s = sA + st * ASZ;
        float* b_s = sB + st * BSZ;
        #pragma unroll
        for (int i = 0; i < 8; i++) {
            int idx = tid + 128 * i;
            int r = idx >> 3, q = idx & 7;
            cp_async16(a_s + r * ASTR + q * 4,
                       Ab + (size_t)(row0 + r) * lda + k0 + q * 4);
        }
        #pragma unroll
        for (int i = 0; i < 8; i++) {
            int idx = tid + 128 * i;
            if (TB) {
                int r = idx >> 3, q = idx & 7;
                cp_async16(b_s + r * ASTR + q * 4,
                           Bb + (size_t)(col0 + r) * ldb + k0 + q * 4);
            } else {
                int bk = idx >> 5, bq = idx & 31;
                cp_async16(b_s + bk * BSTR_N + bq * 4,
                           Bb + (size_t)(k0 + bk) * ldb + col0 + bq * 4);
            }
        }
    };

    int nk = K / BK;
    load_stage(0, 0);
    cp_commit();
    load_stage(1, BK);
    cp_commit();

    for (int i = 0; i < nk; i++) {
        cp_wait<1>();
        __syncthreads();

        // issue loads for stage i+2 (reuses stage (i-1)%3 -- safe: barrier above
        // guarantees all warps finished compute(i-1))
        if (i + 2 < nk) load_stage((i + 2) % 3, (i + 2) * BK);
        cp_commit();

        const uint32_t* a_s = (const uint32_t*)(sA + (i % 3) * ASZ);
        const uint32_t* b_s = (const uint32_t*)(sB + (i % 3) * BSZ);

        #pragma unroll
        for (int kk = 0; kk < 4; kk++) {
            int k8 = kk * 8;
            uint32_t afr[4][4], bfr[8][2];
            #pragma unroll
            for (int mt = 0; mt < 4; mt++) {
                int m_ = wm0 + mt * 16;
                afr[mt][0] = a_s[(m_ + g) * ASTR + k8 + t4];
                afr[mt][1] = a_s[(m_ + g + 8) * ASTR + k8 + t4];
                afr[mt][2] = a_s[(m_ + g) * ASTR + k8 + t4 + 4];
                afr[mt][3] = a_s[(m_ + g + 8) * ASTR + k8 + t4 + 4];
            }
            #pragma unroll
            for (int nt = 0; nt < 8; nt++) {
                int n_ = wn0 + nt * 8 + g;
                if (TB) {
                    bfr[nt][0] = b_s[n_ * ASTR + k8 + t4];
                    bfr[nt][1] = b_s[n_ * ASTR + k8 + t4 + 4];
                } else {
                    bfr[nt][0] = b_s[(k8 + t4) * BSTR_N + n_];
                    bfr[nt][1] = b_s[(k8 + t4 + 4) * BSTR_N + n_];
                }
            }
            #pragma unroll
            for (int mt = 0; mt < 4; mt++)
                #pragma unroll
                for (int nt = 0; nt < 8; nt++)
                    mma_tf32(acc[mt][nt], afr[mt], bfr[nt]);
        }
    }

    // ---- epilogue ----
    #pragma unroll
    for (int mt = 0; mt < 4; mt++) {
        int r0 = row0 + wm0 + mt * 16 + g;
        #pragma unroll
        for (int nt = 0; nt < 8; nt++) {
            int c0c = col0 + wn0 + nt * 8 + 2 * t4;
            float b0 = bias ? bias[c0c] : 0.f;
            float b1 = bias ? bias[c0c + 1] : 0.f;
            float v00 = alpha * acc[mt][nt][0] + b0;
            float v01 = alpha * acc[mt][nt][1] + b1;
            float v10 = alpha * acc[mt][nt][2] + b0;
            float v11 = alpha * acc[mt][nt][3] + b1;
            if (RND) {
                v00 = rnd_tf32(v00); v01 = rnd_tf32(v01);
                v10 = rnd_tf32(v10); v11 = rnd_tf32(v11);
            }
            *(float2*)&Cb[(size_t)r0 * ldc + c0c]       = make_float2(v00, v01);
            *(float2*)&Cb[(size_t)(r0 + 8) * ldc + c0c] = make_float2(v10, v11);
        }
    }
}

// ---------------- 2-stage 256-thread engine (N=576 and K=128 cases) ---------
template<int TN, bool TB, bool RND>
__global__ void __launch_bounds__(256, 2) gemm_tc(
    int M, int N, int K,
    const float* __restrict__ A, int lda, long long sAb, long long sAh,
    const float* __restrict__ Bp, int ldb, long long sBb, long long sBh,
    float* __restrict__ C, int ldc, long long sCb, long long sCh,
    int ZH, float alpha, const float* __restrict__ bias)
{
    constexpr int TM = 128, BK = 32;
    constexpr int WROWS = (TN == 128) ? 2 : 4;
    constexpr int WCOLS = 8 / WROWS;
    constexpr int WM = TM / WROWS;
    constexpr int WN = TN / WCOLS;
    constexpr int MT = WM / 16;
    constexpr int NT4 = WN / 8;
    constexpr int ASTR = BK + 4;
    constexpr int BSTR_N = TN + 8;
    constexpr int ASZ = TM * ASTR;
    constexpr int BSZ = TB ? TN * ASTR : BK * BSTR_N;
    constexpr int AITER = TM * (BK / 4) / 256;
    constexpr int BITER = TN * (BK / 4) / 256;

    extern __shared__ float smemf[];
    float* sA = smemf;
    float* sB = smemf + 2 * ASZ;

    int z  = blockIdx.z;
    int zb = z / ZH;
    int zh = z - zb * ZH;
    const float* Ab = A  + zb * sAb + zh * sAh;
    const float* Bb = Bp + zb * sBb + zh * sBh;
    float*       Cb = C  + zb * sCb + zh * sCh;

    int row0 = blockIdx.y * TM;
    int col0 = blockIdx.x * TN;
    int tid  = threadIdx.x;
    int wid  = tid >> 5;
    int lane = tid & 31;
    int wr = wid / WCOLS, wc = wid % WCOLS;
    int wm0 = wr * WM, wn0 = wc * WN;
    int g = lane >> 2, t4 = lane & 3;

    float acc[MT][NT4][4] = {};

    auto load_stage = [&](int st, int k0) {
        float* a_s = sA + st * ASZ;
        float* b_s = sB + st * BSZ;
        #pragma unroll
        for (int i = 0; i < AITER; i++) {
            int idx = tid + 256 * i;
            int am = idx >> 3, akq = idx & 7;
            cp_async16(a_s + am * ASTR + akq * 4,
                       Ab + (size_t)(row0 + am) * lda + k0 + akq * 4);
        }
        #pragma unroll
        for (int i = 0; i < BITER; i++) {
            int idx = tid + 256 * i;
            if (TB) {
                int bn = idx >> 3, bkq = idx & 7;
                cp_async16(b_s + bn * ASTR + bkq * 4,
                           Bb + (size_t)(col0 + bn) * ldb + k0 + bkq * 4);
            } else {
                int bk = idx / (TN / 4), bnq = idx % (TN / 4);
                cp_async16(b_s + bk * BSTR_N + bnq * 4,
                           Bb + (size_t)(k0 + bk) * ldb + col0 + bnq * 4);
            }
        }
    };

    int nk = K / BK;
    load_stage(0, 0);
    cp_commit();

    for (int i = 0; i < nk; i++) {
        if (i + 1 < nk) load_stage((i + 1) & 1, (i + 1) * BK);
        cp_commit();
        cp_wait<1>();
        __syncthreads();

        int st = i & 1;
        const uint32_t* a_s = (const uint32_t*)(sA + st * ASZ);
        const uint32_t* b_s = (const uint32_t*)(sB + st * BSZ);

        #pragma unroll
        for (int kk = 0; kk < 4; kk++) {
            int k8 = kk * 8;
            uint32_t afr[MT][4], bfr[NT4][2];
            #pragma unroll
            for (int mt = 0; mt < MT; mt++) {
                int m_ = wm0 + mt * 16;
                afr[mt][0] = a_s[(m_ + g) * ASTR + k8 + t4];
                afr[mt][1] = a_s[(m_ + g + 8) * ASTR + k8 + t4];
                afr[mt][2] = a_s[(m_ + g) * ASTR + k8 + t4 + 4];
                afr[mt][3] = a_s[(m_ + g + 8) * ASTR + k8 + t4 + 4];
            }
            #pragma unroll
            for (int nt = 0; nt < NT4; nt++) {
                int n_ = wn0 + nt * 8 + g;
                if (TB) {
                    bfr[nt][0] = b_s[n_ * ASTR + k8 + t4];
                    bfr[nt][1] = b_s[n_ * ASTR + k8 + t4 + 4];
                } else {
                    bfr[nt][0] = b_s[(k8 + t4) * BSTR_N + n_];
                    bfr[nt][1] = b_s[(k8 + t4 + 4) * BSTR_N + n_];
                }
            }
            #pragma unroll
            for (int mt = 0; mt < MT; mt++)
                #pragma unroll
                for (int nt = 0; nt < NT4; nt++)
                    mma_tf32(acc[mt][nt], afr[mt], bfr[nt]);
        }
        __syncthreads();
    }

    #pragma unroll
    for (int mt = 0; mt < MT; mt++) {
        int r0 = row0 + wm0 + mt * 16 + g;
        #pragma unroll
        for (int nt = 0; nt < NT4; nt++) {
            int c0c = col0 + wn0 + nt * 8 + 2 * t4;
            float b0 = bias ? bias[c0c] : 0.f;
            float b1 = bias ? bias[c0c + 1] : 0.f;
            float v00 = alpha * acc[mt][nt][0] + b0;
            float v01 = alpha * acc[mt][nt][1] + b1;
            float v10 = alpha * acc[mt][nt][2] + b0;
            float v11 = alpha * acc[mt][nt][3] + b1;
            if (RND) {
                v00 = rnd_tf32(v00); v01 = rnd_tf32(v01);
                v10 = rnd_tf32(v10); v11 = rnd_tf32(v11);
            }
            *(float2*)&Cb[(size_t)r0 * ldc + c0c]       = make_float2(v00, v01);
            *(float2*)&Cb[(size_t)(r0 + 8) * ldc + c0c] = make_float2(v10, v11);
        }
    }
}

// ---------------- elementwise kernels ----------------------------------------
__global__ void round_copy_k(const float* __restrict__ in, float* __restrict__ out)
{
    size_t i = ((size_t)blockIdx.x * 256 + threadIdx.x) * 4;
    float4 v = *(const float4*)(in + i);
    v.x = rnd_tf32(v.x); v.y = rnd_tf32(v.y);
    v.z = rnd_tf32(v.z); v.w = rnd_tf32(v.w);
    *(float4*)(out + i) = v;
}

__global__ void rmsnorm_k(const float* __restrict__ in, float* __restrict__ out,
                          const float* __restrict__ w, int width,
                          int inStride, int outStride)
{
    int row = blockIdx.x;
    const float* ip = in  + (size_t)row * inStride;
    float*       op = out + (size_t)row * outStride;
    float ss = 0.f;
    for (int i = threadIdx.x; i < width; i += 256) {
        float v = ip[i];
        ss += v * v;
    }
    __shared__ float sm[256];
    sm[threadIdx.x] = ss;
    __syncthreads();
    for (int s = 128; s > 0; s >>= 1) {
        if (threadIdx.x < s) sm[threadIdx.x] += sm[threadIdx.x + s];
        __syncthreads();
    }
    float r = rsqrtf(sm[0] / (float)width + 1e-3f);
    for (int i = threadIdx.x; i < width; i += 256)
        op[i] = rnd_tf32(w[i] * ip[i] * r);
}

__global__ void rope_q_k(const float* __restrict__ q, float* __restrict__ qf,
                         const float* __restrict__ c, const float* __restrict__ s)
{
    int tok = blockIdx.x;
    int h = threadIdx.x >> 5;
    int j = threadIdx.x & 31;
    int pos = tok % S_;
    const float* src = q  + (size_t)tok * HQK + h * QK_ + NOPE_;
    float*       dst = qf + (size_t)tok * HQF + h * KFW + KVL;
    float xr = src[2 * j], xi = src[2 * j + 1];
    float cc = c[pos * 32 + j], sn = s[pos * 32 + j];
    dst[2 * j]     = rnd_tf32(xr * cc - xi * sn);
    dst[2 * j + 1] = rnd_tf32(xr * sn + xi * cc);
}

__global__ void rope_k_k(const float* __restrict__ kvf, float* __restrict__ kf,
                         const float* __restrict__ c, const float* __restrict__ s)
{
    int tok = blockIdx.x;
    int j = threadIdx.x;
    int pos = tok % S_;
    const float* src = kvf + (size_t)tok * KFW + KVL;
    float*       dst = kf  + (size_t)tok * KFW + KVL;
    float xr = src[2 * j], xi = src[2 * j + 1];
    float cc = c[pos * 32 + j], sn = s[pos * 32 + j];
    dst[2 * j]     = rnd_tf32(xr * cc - xi * sn);
    dst[2 * j + 1] = rnd_tf32(xr * sn + xi * cc);
}

__global__ void softmax_k(float* __restrict__ d)
{
    size_t row = blockIdx.x;
    float* p = d + row * (size_t)S_;
    int t = threadIdx.x;
    float v[8];
    float m = -INFINITY;
    #pragma unroll
    for (int i = 0; i < 8; i++) {
        v[i] = p[t + i * 256];
        m = fmaxf(m, v[i]);
    }
    __shared__ float sm[256];
    sm[t] = m;
    __syncthreads();
    for (int s = 128; s > 0; s >>= 1) {
        if (t < s) sm[t] = fmaxf(sm[t], sm[t + s]);
        __syncthreads();
    }
    m = sm[0];
    __syncthreads();
    float sum = 0.f;
    #pragma unroll
    for (int i = 0; i < 8; i++) {
        v[i] = __expf(v[i] - m);
        sum += v[i];
    }
    sm[t] = sum;
    __syncthreads();
    for (int s = 128; s > 0; s >>= 1) {
        if (t < s) sm[t] += sm[t + s];
        __syncthreads();
    }
    float inv = 1.f / sm[0];
    #pragma unroll
    for (int i = 0; i < 8; i++)
        p[t + i * 256] = rnd_tf32(v[i] * inv);
}

// ---------------- host glue --------------------------------------------------
template<bool TB, bool RND>
static void launch_w64(int M, int N, int K,
                       const float* A, int lda, long long sAb, long long sAh,
                       const float* Bp, int ldb, long long sBb, long long sBh,
                       float* C, int ldc, long long sCb, long long sCh,
                       int nb, int nh, float alpha, const float* bias)
{
    constexpr int ASZ = 128 * 36;
    constexpr int BSZ = TB ? 128 * 36 : 32 * 136;
    constexpr int SMEM = (3 * ASZ + 3 * BSZ) * 4;
    cudaFuncSetAttribute(gemm_w64<TB, RND>,
                         cudaFuncAttributeMaxDynamicSharedMemorySize, SMEM);
    dim3 grid(N / 128, M / 128, nb * nh);
    gemm_w64<TB, RND><<<grid, 128, SMEM>>>(K, A, lda, sAb, sAh,
                                           Bp, ldb, sBb, sBh,
                                           C, ldc, sCb, sCh, nh, alpha, bias);
}

template<int TN, bool TB, bool RND>
static void launch_tc(int M, int N, int K,
                      const float* A, int lda, long long sAb, long long sAh,
                      const float* Bp, int ldb, long long sBb, long long sBh,
                      float* C, int ldc, long long sCb, long long sCh,
                      int nb, int nh, float alpha, const float* bias)
{
    constexpr int ASZ = 128 * 36;
    constexpr int BSZ = TB ? TN * 36 : 32 * (TN + 8);
    constexpr int SMEM = (2 * ASZ + 2 * BSZ) * 4;
    cudaFuncSetAttribute(gemm_tc<TN, TB, RND>,
                         cudaFuncAttributeMaxDynamicSharedMemorySize, SMEM);
    dim3 grid(N / TN, M / 128, nb * nh);
    gemm_tc<TN, TB, RND><<<grid, 256, SMEM>>>(M, N, K, A, lda, sAb, sAh,
                                              Bp, ldb, sBb, sBh,
                                              C, ldc, sCb, sCh, nh, alpha, bias);
}

static void round_copy(const float* in, float* out, size_t n)
{
    round_copy_k<<<(unsigned)(n / 1024), 256>>>(in, out);
}

extern "C" void kernel_launch(void* const* d_in, const int* in_sizes, int n_in,
                              void* d_out, int out_size)
{
    const float* x        = (const float*)d_in[0];
    const float* cosp     = (const float*)d_in[2];
    const float* sinp     = (const float*)d_in[3];
    const float* wq_a_w   = (const float*)d_in[4];
    const float* wq_a_b   = (const float*)d_in[5];
    const float* q_norm_w = (const float*)d_in[6];
    const float* wq_b_w   = (const float*)d_in[7];
    const float* wq_b_b   = (const float*)d_in[8];
    const float* wkv_a_w  = (const float*)d_in[9];
    const float* wkv_a_b  = (const float*)d_in[10];
    const float* kv_norm_w= (const float*)d_in[11];
    const float* wkv_b_w  = (const float*)d_in[12];
    const float* wo_w     = (const float*)d_in[13];
    const float* wo_b     = (const float*)d_in[14];
    float* out = (float*)d_out;

    float *qa, *q, *kvf, *qf, *kf, *sc, *om, *oc;
    float *xr, *wqa, *wqb, *wkva, *wkvb, *wo;
    cudaGetSymbolAddress((void**)&qa,  g_qa);
    cudaGetSymbolAddress((void**)&q,   g_q);
    cudaGetSymbolAddress((void**)&kvf, g_kvfull);
    cudaGetSymbolAddress((void**)&qf,  g_qf);
    cudaGetSymbolAddress((void**)&kf,  g_kf);
    cudaGetSymbolAddress((void**)&sc,  g_scores);
    cudaGetSymbolAddress((void**)&om,  g_omid);
    cudaGetSymbolAddress((void**)&oc,  g_ocat);
    cudaGetSymbolAddress((void**)&xr,  g_xr);
    cudaGetSymbolAddress((void**)&wqa, g_wqa_r);
    cudaGetSymbolAddress((void**)&wqb, g_wqb_r);
    cudaGetSymbolAddress((void**)&wkva,g_wkva_r);
    cudaGetSymbolAddress((void**)&wkvb,g_wkvb_r);
    cudaGetSymbolAddress((void**)&wo,  g_wo_r);

    // 0) tf32-round inputs once
    round_copy(x,       xr,   (size_t)NT * D_);
    round_copy(wq_a_w,  wqa,  (size_t)QL * D_);
    round_copy(wq_b_w,  wqb,  (size_t)HQK * QL);
    round_copy(wkv_a_w, wkva, (size_t)KFW * D_);
    round_copy(wkv_b_w, wkvb, (size_t)H_ * (NOPE_ + VH_) * KVL);
    round_copy(wo_w,    wo,   (size_t)D_ * H_ * VH_);

    // 1) q_a = x @ wq_a^T + b          [4096,1024] K=2048
    launch_w64<true, false>(NT, QL, D_, xr, D_, 0, 0, wqa, D_, 0, 0,
                            qa, QL, 0, 0, 1, 1, 1.f, wq_a_b);
    // 2) rmsnorm(q_a) in place (rounded)
    rmsnorm_k<<<NT, 256>>>(qa, qa, q_norm_w, QL, QL, QL);
    // 3) q = q_a_n @ wq_b^T + b        [4096,3072] K=1024 (rounded: feeds GEMM 8)
    launch_w64<true, true>(NT, HQK, QL, qa, QL, 0, 0, wqb, QL, 0, 0,
                           q, HQK, 0, 0, 1, 1, 1.f, wq_b_b);
    // 4) kv_full = x @ wkv_a^T + b     [4096,576] K=2048 (N=576 -> old engine)
    launch_tc<64, true, false>(NT, KFW, D_, xr, D_, 0, 0, wkva, D_, 0, 0,
                               kvf, KFW, 0, 0, 1, 1, 1.f, wkv_a_b);
    // 5) kf[:, :512] = rmsnorm(kv_full[:, :512]) (rounded)
    rmsnorm_k<<<NT, 256>>>(kvf, kf, kv_norm_w, KVL, KFW, KFW);
    // 6) kf[:, 512:576] = rope(k_pe) (rounded)
    rope_k_k<<<NT, 32>>>(kvf, kf, cosp, sinp);
    // 7) qf[:, h, 512:576] = rope(q_pe) (rounded)
    rope_q_k<<<NT, 512>>>(q, qf, cosp, sinp);
    // 8) qf[:, h, :512] = q_nope_h @ wkv_b[h,:128,:] (NN, K=128 -> old engine)
    launch_tc<128, false, true>(NT, KVL, NOPE_,
                                q, HQK, 0, QK_,
                                wkvb, KVL, 0, (long long)(NOPE_ + VH_) * KVL,
                                qf, HQF, 0, KFW,
                                1, H_, 1.f, nullptr);
    // 9) scores = SCALE * qf @ kf^T    [2048,2048]x32 K=576
    launch_w64<true, false>(S_, S_, KFW,
                            qf, HQF, (long long)S_ * HQF, KFW,
                            kf, KFW, (long long)S_ * KFW, 0,
                            sc, S_, (long long)H_ * S_ * S_, (long long)S_ * S_,
                            B_, H_, SCALE, nullptr);
    // 10) softmax rows (rounded output)
    softmax_k<<<B_ * H_ * S_, 256>>>(sc);
    // 11) o_mid = probs @ kv_c         (NN) [2048,512]x32 K=2048
    launch_w64<false, true>(S_, KVL, S_,
                            sc, S_, (long long)H_ * S_ * S_, (long long)S_ * S_,
                            kf, KFW, (long long)S_ * KFW, 0,
                            om, H_ * KVL, (long long)S_ * H_ * KVL, KVL,
                            B_, H_, 1.f, nullptr);
    // 12) o_cat = o_mid @ wkv_b_v^T    [4096,128]x16 K=512 (rounded)
    launch_w64<true, true>(NT, VH_, KVL,
                           om, H_ * KVL, 0, KVL,
                           wkvb + (size_t)NOPE_ * KVL, KVL, 0,
                           (long long)(NOPE_ + VH_) * KVL,
                           oc, H_ * VH_, 0, VH_,
                           1, H_, 1.f, nullptr);
    // 13) out = o_cat @ wo^T + b       [4096,2048] K=2048 (final: fp32)
    launch_w64<true, false>(NT, D_, H_ * VH_, oc, H_ * VH_, 0, 0, wo, D_, 0, 0,
                            out, D_, 0, 0, 1, 1, 1.f, wo_b);
}

// round 7
// speedup vs baseline: 6.8126x; 1.5437x over previous
#include <cuda_runtime.h>
#include <cuda_fp16.h>
#include <math.h>
#include <stdint.h>

#define B_    2
#define S_    2048
#define D_    2048
#define H_    16
#define NT    4096          // B_*S_
#define QL    1024
#define KVL   512
#define NOPE_ 128
#define ROPE_ 64
#define VH_   128
#define QK_   192
#define KFW   576           // KVL + ROPE
#define KVP   640           // padded kv_full width
#define HQK   3072          // H_*QK_
#define HQF   9216          // H_*KFW
#define SCALE 0.07216878364870322f   // 192^-0.5

// ---------------- scratch (static device globals; no runtime alloc) -------
__device__ __align__(256) __half h_x  [(size_t)NT * D_];
__device__ __align__(256) __half h_qa [(size_t)NT * QL];
__device__ __align__(256) __half h_q  [(size_t)NT * HQK];
__device__ __align__(256) __half h_kvf[(size_t)NT * KVP];
__device__ __align__(256) __half h_qf [(size_t)NT * HQF];
__device__ __align__(256) __half h_kf [(size_t)NT * KFW];
__device__ __align__(256) __half h_kfT[(size_t)B_ * KVL * S_];
__device__ __align__(256) float  g_scores[(size_t)B_ * H_ * S_ * S_];
__device__ __align__(256) __half h_probs [(size_t)B_ * H_ * S_ * S_];
__device__ __align__(256) __half h_om [(size_t)NT * H_ * KVL];
__device__ __align__(256) __half h_oc [(size_t)NT * H_ * VH_];
__device__ __align__(256) __half h_wqa[(size_t)QL * D_];
__device__ __align__(256) __half h_wqb[(size_t)HQK * QL];
__device__ __align__(256) __half h_wkva[(size_t)KVP * D_];
__device__ __align__(256) __half h_wkvb[(size_t)H_ * 256 * KVL];
__device__ __align__(256) __half h_wkvbT[(size_t)H_ * KVL * NOPE_];
__device__ __align__(256) __half h_wo [(size_t)D_ * H_ * VH_];
__device__ float g_biaskva[KVP];

// ---------------- helpers ---------------------------------------------------
__device__ __forceinline__ void mma_f16(float* c, const uint32_t* a, const uint32_t* b) {
    asm volatile(
        "mma.sync.aligned.m16n8k16.row.col.f32.f16.f16.f32 "
        "{%0,%1,%2,%3},{%4,%5,%6,%7},{%8,%9},{%0,%1,%2,%3};"
        : "+f"(c[0]), "+f"(c[1]), "+f"(c[2]), "+f"(c[3])
        : "r"(a[0]), "r"(a[1]), "r"(a[2]), "r"(a[3]), "r"(b[0]), "r"(b[1]));
}

__device__ __forceinline__ void cp_async16(void* smem, const void* gmem) {
    uint32_t s = (uint32_t)__cvta_generic_to_shared(smem);
    asm volatile("cp.async.cg.shared.global [%0], [%1], 16;" :: "r"(s), "l"(gmem));
}
__device__ __forceinline__ void cp_commit() {
    asm volatile("cp.async.commit_group;");
}
template<int N>
__device__ __forceinline__ void cp_wait() {
    asm volatile("cp.async.wait_group %0;" :: "n"(N));
}

// =============================================================================
// gemm_h: fp16 in / fp32 acc. 128x128 CTA tile, 128 threads (4 warps, 2x2),
// warp tile 64x64, BK=32, 3-stage cp.async, one __syncthreads per K-tile.
// C[z] = alpha * A[z] @ B[z]^T + bias.  A [M,K], B [N,K], both half row-major.
// =============================================================================
template<bool OUTHALF>
__global__ void __launch_bounds__(128) gemm_h(
    int K,
    const __half* __restrict__ A, int lda, long long sAb, long long sAh,
    const __half* __restrict__ Bp, int ldb, long long sBb, long long sBh,
    void* __restrict__ Cv, int ldc, long long sCb, long long sCh,
    int ZH, float alpha, const float* __restrict__ bias)
{
    constexpr int ASTR = 20;                 // u32 per row: 16 data + 4 pad (80B, 16B-aligned rows)
    constexpr int STG = 128 * ASTR;          // u32 per stage (A or B)

    extern __shared__ uint32_t smu[];
    uint32_t* sA = smu;                      // [3][STG]
    uint32_t* sB = smu + 3 * STG;            // [3][STG]

    int z  = blockIdx.z;
    int zb = z / ZH;
    int zh = z - zb * ZH;
    const __half* Ab = A  + zb * sAb + zh * sAh;
    const __half* Bb = Bp + zb * sBb + zh * sBh;

    int row0 = blockIdx.y << 7;
    int col0 = blockIdx.x << 7;
    int tid  = threadIdx.x;
    int wid  = tid >> 5;
    int lane = tid & 31;
    int wm0 = (wid >> 1) << 6;
    int wn0 = (wid & 1) << 6;
    int g = lane >> 2, t4 = lane & 3;

    float acc[4][8][4] = {};

    auto load_stage = [&](int st, int k0) {
        uint32_t* a_s = sA + st * STG;
        uint32_t* b_s = sB + st * STG;
        #pragma unroll
        for (int i = 0; i < 4; i++) {
            int idx = tid + 128 * i;
            int r = idx >> 2, q = idx & 3;          // 16B chunk q of row r (64B rows)
            cp_async16(a_s + r * ASTR + q * 4,
                       Ab + (size_t)(row0 + r) * lda + k0 + q * 8);
        }
        #pragma unroll
        for (int i = 0; i < 4; i++) {
            int idx = tid + 128 * i;
            int r = idx >> 2, q = idx & 3;
            cp_async16(b_s + r * ASTR + q * 4,
                       Bb + (size_t)(col0 + r) * ldb + k0 + q * 8);
        }
    };

    int nk = K / 32;
    load_stage(0, 0);
    cp_commit();
    load_stage(1, 32);
    cp_commit();

    for (int i = 0; i < nk; i++) {
        cp_wait<1>();
        __syncthreads();
        if (i + 2 < nk) load_stage((i + 2) % 3, (i + 2) * 32);
        cp_commit();

        const uint32_t* a_s = sA + (i % 3) * STG;
        const uint32_t* b_s = sB + (i % 3) * STG;

        #pragma unroll
        for (int kk = 0; kk < 2; kk++) {
            int k8 = kk * 8;
            uint32_t afr[4][4], bfr[8][2];
            #pragma unroll
            for (int mt = 0; mt < 4; mt++) {
                int m_ = wm0 + mt * 16;
                afr[mt][0] = a_s[(m_ + g) * ASTR + k8 + t4];
                afr[mt][1] = a_s[(m_ + g + 8) * ASTR + k8 + t4];
                afr[mt][2] = a_s[(m_ + g) * ASTR + k8 + t4 + 4];
                afr[mt][3] = a_s[(m_ + g + 8) * ASTR + k8 + t4 + 4];
            }
            #pragma unroll
            for (int nt = 0; nt < 8; nt++) {
                int n_ = wn0 + nt * 8 + g;
                bfr[nt][0] = b_s[n_ * ASTR + k8 + t4];
                bfr[nt][1] = b_s[n_ * ASTR + k8 + t4 + 4];
            }
            #pragma unroll
            for (int mt = 0; mt < 4; mt++)
                #pragma unroll
                for (int nt = 0; nt < 8; nt++)
                    mma_f16(acc[mt][nt], afr[mt], bfr[nt]);
        }
    }

    // ---- epilogue ----
    size_t coff = (size_t)zb * sCb + (size_t)zh * sCh;
    #pragma unroll
    for (int mt = 0; mt < 4; mt++) {
        int r0 = row0 + wm0 + mt * 16 + g;
        #pragma unroll
        for (int nt = 0; nt < 8; nt++) {
            int c0c = col0 + wn0 + nt * 8 + 2 * t4;
            float b0 = bias ? bias[c0c] : 0.f;
            float b1 = bias ? bias[c0c + 1] : 0.f;
            float v00 = alpha * acc[mt][nt][0] + b0;
            float v01 = alpha * acc[mt][nt][1] + b1;
            float v10 = alpha * acc[mt][nt][2] + b0;
            float v11 = alpha * acc[mt][nt][3] + b1;
            if (OUTHALF) {
                __half* Ch = (__half*)Cv + coff;
                *(__half2*)&Ch[(size_t)r0 * ldc + c0c]       = __floats2half2_rn(v00, v01);
                *(__half2*)&Ch[(size_t)(r0 + 8) * ldc + c0c] = __floats2half2_rn(v10, v11);
            } else {
                float* Cf = (float*)Cv + coff;
                *(float2*)&Cf[(size_t)r0 * ldc + c0c]       = make_float2(v00, v01);
                *(float2*)&Cf[(size_t)(r0 + 8) * ldc + c0c] = make_float2(v10, v11);
            }
        }
    }
}

// ---------------- prepass kernels --------------------------------------------
__global__ void f2h_k(const float* __restrict__ in, __half* __restrict__ out)
{
    size_t i = ((size_t)blockIdx.x * 256 + threadIdx.x) * 4;
    float4 v = *(const float4*)(in + i);
    __half2* o = (__half2*)(out + i);
    o[0] = __floats2half2_rn(v.x, v.y);
    o[1] = __floats2half2_rn(v.z, v.w);
}

// wkva padded to [640][2048]: rows >=576 are zero
__global__ void wkva_pad_k(const float* __restrict__ in, __half* __restrict__ out)
{
    size_t i = ((size_t)blockIdx.x * 256 + threadIdx.x) * 4;
    if (i < (size_t)KFW * D_) {
        float4 v = *(const float4*)(in + i);
        __half2* o = (__half2*)(out + i);
        o[0] = __floats2half2_rn(v.x, v.y);
        o[1] = __floats2half2_rn(v.z, v.w);
    } else {
        __half2* o = (__half2*)(out + i);
        o[0] = __half2{__half(0.f), __half(0.f)};
        o[1] = __half2{__half(0.f), __half(0.f)};
    }
}

__global__ void biaskva_pad_k(const float* __restrict__ in, float* __restrict__ out)
{
    int i = blockIdx.x * 256 + threadIdx.x;
    if (i < KVP) out[i] = (i < KFW) ? in[i] : 0.f;
}

// wkvbT[h][c][r] = wkvb[h*256 + r][c], r<128, c<512
__global__ void wkvbT_k(const float* __restrict__ in, __half* __restrict__ out)
{
    __shared__ float t[32][33];
    int h = blockIdx.z;
    int r0 = blockIdx.x * 32;
    int c0 = blockIdx.y * 32;
    int x = threadIdx.x, y = threadIdx.y;
    #pragma unroll
    for (int i = 0; i < 32; i += 8)
        t[y + i][x] = in[(size_t)(h * 256 + r0 + y + i) * KVL + c0 + x];
    __syncthreads();
    #pragma unroll
    for (int i = 0; i < 32; i += 8)
        out[(size_t)h * KVL * NOPE_ + (size_t)(c0 + y + i) * NOPE_ + r0 + x] =
            __float2half(t[x][y + i]);
}

// kfT[b][c][t] = kf[b][t][c], c<512
__global__ void kfT_k(const __half* __restrict__ kf, __half* __restrict__ kfT)
{
    __shared__ __half t[32][33];
    int b = blockIdx.z;
    int t0 = blockIdx.x * 32;
    int c0 = blockIdx.y * 32;
    int x = threadIdx.x, y = threadIdx.y;
    const __half* src = kf + (size_t)b * S_ * KFW;
    #pragma unroll
    for (int i = 0; i < 32; i += 8)
        t[y + i][x] = src[(size_t)(t0 + y + i) * KFW + c0 + x];
    __syncthreads();
    __half* dst = kfT + (size_t)b * KVL * S_;
    #pragma unroll
    for (int i = 0; i < 32; i += 8)
        dst[(size_t)(c0 + y + i) * S_ + t0 + x] = t[x][y + i];
}

// ---------------- elementwise kernels (half I/O) ------------------------------
__global__ void rmsnorm_h(const __half* __restrict__ in, __half* __restrict__ out,
                          const float* __restrict__ w, int width,
                          int inStride, int outStride)
{
    int row = blockIdx.x;
    const __half* ip = in  + (size_t)row * inStride;
    __half*       op = out + (size_t)row * outStride;
    float ss = 0.f;
    for (int i = threadIdx.x; i < width; i += 256) {
        float v = __half2float(ip[i]);
        ss += v * v;
    }
    __shared__ float sm[256];
    sm[threadIdx.x] = ss;
    __syncthreads();
    for (int s = 128; s > 0; s >>= 1) {
        if (threadIdx.x < s) sm[threadIdx.x] += sm[threadIdx.x + s];
        __syncthreads();
    }
    float r = rsqrtf(sm[0] / (float)width + 1e-3f);
    for (int i = threadIdx.x; i < width; i += 256)
        op[i] = __float2half(w[i] * __half2float(ip[i]) * r);
}

__global__ void rope_q_h(const __half* __restrict__ q, __half* __restrict__ qf,
                         const float* __restrict__ c, const float* __restrict__ s)
{
    int tok = blockIdx.x;
    int h = threadIdx.x >> 5;
    int j = threadIdx.x & 31;
    int pos = tok % S_;
    const __half* src = q  + (size_t)tok * HQK + h * QK_ + NOPE_;
    __half*       dst = qf + (size_t)tok * HQF + h * KFW + KVL;
    float xr = __half2float(src[2 * j]), xi = __half2float(src[2 * j + 1]);
    float cc = c[pos * 32 + j], sn = s[pos * 32 + j];
    dst[2 * j]     = __float2half(xr * cc - xi * sn);
    dst[2 * j + 1] = __float2half(xr * sn + xi * cc);
}

__global__ void rope_k_h(const __half* __restrict__ kvf, __half* __restrict__ kf,
                         const float* __restrict__ c, const float* __restrict__ s)
{
    int tok = blockIdx.x;
    int j = threadIdx.x;
    int pos = tok % S_;
    const __half* src = kvf + (size_t)tok * KVP + KVL;
    __half*       dst = kf  + (size_t)tok * KFW + KVL;
    float xr = __half2float(src[2 * j]), xi = __half2float(src[2 * j + 1]);
    float cc = c[pos * 32 + j], sn = s[pos * 32 + j];
    dst[2 * j]     = __float2half(xr * cc - xi * sn);
    dst[2 * j + 1] = __float2half(xr * sn + xi * cc);
}

// softmax: fp32 scores in, half probs out
__global__ void softmax_h(const float* __restrict__ d, __half* __restrict__ pr)
{
    size_t row = blockIdx.x;
    const float* p = d + row * (size_t)S_;
    __half* ph = pr + row * (size_t)S_;
    int t = threadIdx.x;
    float v[8];
    float m = -INFINITY;
    #pragma unroll
    for (int i = 0; i < 8; i++) {
        v[i] = p[t + i * 256];
        m = fmaxf(m, v[i]);
    }
    __shared__ float sm[256];
    sm[t] = m;
    __syncthreads();
    for (int s = 128; s > 0; s >>= 1) {
        if (t < s) sm[t] = fmaxf(sm[t], sm[t + s]);
        __syncthreads();
    }
    m = sm[0];
    __syncthreads();
    float sum = 0.f;
    #pragma unroll
    for (int i = 0; i < 8; i++) {
        v[i] = __expf(v[i] - m);
        sum += v[i];
    }
    sm[t] = sum;
    __syncthreads();
    for (int s = 128; s > 0; s >>= 1) {
        if (t < s) sm[t] += sm[t + s];
        __syncthreads();
    }
    float inv = 1.f / sm[0];
    #pragma unroll
    for (int i = 0; i < 8; i++)
        ph[t + i * 256] = __float2half(v[i] * inv);
}

// ---------------- host glue --------------------------------------------------
template<bool OUTHALF>
static void launch_h(int M, int N, int K,
                     const __half* A, int lda, long long sAb, long long sAh,
                     const __half* Bp, int ldb, long long sBb, long long sBh,
                     void* C, int ldc, long long sCb, long long sCh,
                     int nb, int nh, float alpha, const float* bias)
{
    constexpr int SMEM = 6 * 128 * 20 * 4;   // 61440 B
    cudaFuncSetAttribute(gemm_h<OUTHALF>,
                         cudaFuncAttributeMaxDynamicSharedMemorySize, SMEM);
    dim3 grid(N / 128, M / 128, nb * nh);
    gemm_h<OUTHALF><<<grid, 128, SMEM>>>(K, A, lda, sAb, sAh, Bp, ldb, sBb, sBh,
                                         C, ldc, sCb, sCh, nh, alpha, bias);
}

static void f2h(const float* in, __half* out, size_t n)
{
    f2h_k<<<(unsigned)(n / 1024), 256>>>(in, out);
}

extern "C" void kernel_launch(void* const* d_in, const int* in_sizes, int n_in,
                              void* d_out, int out_size)
{
    const float* x        = (const float*)d_in[0];
    const float* cosp     = (const float*)d_in[2];
    const float* sinp     = (const float*)d_in[3];
    const float* wq_a_w   = (const float*)d_in[4];
    const float* wq_a_b   = (const float*)d_in[5];
    const float* q_norm_w = (const float*)d_in[6];
    const float* wq_b_w   = (const float*)d_in[7];
    const float* wq_b_b   = (const float*)d_in[8];
    const float* wkv_a_w  = (const float*)d_in[9];
    // d_in[10] = wkv_a_b
    const float* kv_norm_w= (const float*)d_in[11];
    const float* wkv_b_w  = (const float*)d_in[12];
    const float* wo_w     = (const float*)d_in[13];
    const float* wo_b     = (const float*)d_in[14];
    float* out = (float*)d_out;

    __half *xh, *qa, *q, *kvf, *qf, *kf, *kfT, *probs, *om, *oc;
    __half *wqa, *wqb, *wkva, *wkvb, *wkvbT, *wo;
    float *sc, *bkva;
    cudaGetSymbolAddress((void**)&xh,   h_x);
    cudaGetSymbolAddress((void**)&qa,   h_qa);
    cudaGetSymbolAddress((void**)&q,    h_q);
    cudaGetSymbolAddress((void**)&kvf,  h_kvf);
    cudaGetSymbolAddress((void**)&qf,   h_qf);
    cudaGetSymbolAddress((void**)&kf,   h_kf);
    cudaGetSymbolAddress((void**)&kfT,  h_kfT);
    cudaGetSymbolAddress((void**)&sc,   g_scores);
    cudaGetSymbolAddress((void**)&probs,h_probs);
    cudaGetSymbolAddress((void**)&om,   h_om);
    cudaGetSymbolAddress((void**)&oc,   h_oc);
    cudaGetSymbolAddress((void**)&wqa,  h_wqa);
    cudaGetSymbolAddress((void**)&wqb,  h_wqb);
    cudaGetSymbolAddress((void**)&wkva, h_wkva);
    cudaGetSymbolAddress((void**)&wkvb, h_wkvb);
    cudaGetSymbolAddress((void**)&wkvbT,h_wkvbT);
    cudaGetSymbolAddress((void**)&wo,   h_wo);
    cudaGetSymbolAddress((void**)&bkva, g_biaskva);

    // 0) convert inputs to half
    f2h(x,      xh,  (size_t)NT * D_);
    f2h(wq_a_w, wqa, (size_t)QL * D_);
    f2h(wq_b_w, wqb, (size_t)HQK * QL);
    f2h(wkv_b_w,wkvb,(size_t)H_ * 256 * KVL);
    f2h(wo_w,   wo,  (size_t)D_ * H_ * VH_);
    wkva_pad_k<<<(unsigned)((size_t)KVP * D_ / 1024), 256>>>(wkv_a_w, wkva);
    biaskva_pad_k<<<3, 256>>>((const float*)d_in[10], bkva);
    {
        dim3 g(NOPE_ / 32, KVL / 32, H_);
        wkvbT_k<<<g, dim3(32, 8)>>>(wkv_b_w, wkvbT);
    }

    // 1) q_a = x @ wq_a^T + b          [4096,1024] K=2048 -> half
    launch_h<true>(NT, QL, D_, xh, D_, 0, 0, wqa, D_, 0, 0,
                   qa, QL, 0, 0, 1, 1, 1.f, wq_a_b);
    // 2) rmsnorm(q_a) in place
    rmsnorm_h<<<NT, 256>>>(qa, qa, q_norm_w, QL, QL, QL);
    // 3) q = q_a_n @ wq_b^T + b        [4096,3072] K=1024 -> half
    launch_h<true>(NT, HQK, QL, qa, QL, 0, 0, wqb, QL, 0, 0,
                   q, HQK, 0, 0, 1, 1, 1.f, wq_b_b);
    // 4) kv_full = x @ wkva_pad^T + b  [4096,640] K=2048 -> half (ld 640)
    launch_h<true>(NT, KVP, D_, xh, D_, 0, 0, wkva, D_, 0, 0,
                   kvf, KVP, 0, 0, 1, 1, 1.f, bkva);
    // 5) kf[:, :512] = rmsnorm(kv_full[:, :512])
    rmsnorm_h<<<NT, 256>>>(kvf, kf, kv_norm_w, KVL, KVP, KFW);
    // 6) kf[:, 512:576] = rope(k_pe)
    rope_k_h<<<NT, 32>>>(kvf, kf, cosp, sinp);
    // 7) qf[:, h, 512:576] = rope(q_pe)
    rope_q_h<<<NT, 512>>>(q, qf, cosp, sinp);
    // 8) qf[:, h, :512] = q_nope_h @ wkvbT[h]^T  [4096,512] K=128, x16 heads
    launch_h<true>(NT, KVL, NOPE_,
                   q, HQK, 0, QK_,
                   wkvbT, NOPE_, 0, (long long)KVL * NOPE_,
                   qf, HQF, 0, KFW,
                   1, H_, 1.f, nullptr);
    // 8b) kfT[b] = kv_c[b]^T  [512,2048] per batch (after step 5)
    {
        dim3 g(S_ / 32, KVL / 32, B_);
        kfT_k<<<g, dim3(32, 8)>>>(kf, kfT);
    }
    // 9) scores = SCALE * qf @ kf^T    [2048,2048]x32 K=576 -> fp32
    launch_h<false>(S_, S_, KFW,
                    qf, HQF, (long long)S_ * HQF, KFW,
                    kf, KFW, (long long)S_ * KFW, 0,
                    sc, S_, (long long)H_ * S_ * S_, (long long)S_ * S_,
                    B_, H_, SCALE, nullptr);
    // 10) softmax rows -> half probs
    softmax_h<<<B_ * H_ * S_, 256>>>(sc, probs);
    // 11) o_mid = probs @ kfT^T        [2048,512]x32 K=2048 -> half
    launch_h<true>(S_, KVL, S_,
                   probs, S_, (long long)H_ * S_ * S_, (long long)S_ * S_,
                   kfT, S_, (long long)KVL * S_, 0,
                   om, H_ * KVL, (long long)S_ * H_ * KVL, KVL,
                   B_, H_, 1.f, nullptr);
    // 12) o_cat = o_mid @ wkvb_v^T     [4096,128] K=512, x16 heads -> half
    launch_h<true>(NT, VH_, KVL,
                   om, H_ * KVL, 0, KVL,
                   wkvb + (size_t)NOPE_ * KVL, KVL, 0, (long long)256 * KVL,
                   oc, H_ * VH_, 0, VH_,
                   1, H_, 1.f, nullptr);
    // 13) out = o_cat @ wo^T + b       [4096,2048] K=2048 -> fp32
    launch_h<false>(NT, D_, H_ * VH_, oc, H_ * VH_, 0, 0, wo, D_, 0, 0,
                    out, D_, 0, 0, 1, 1, 1.f, wo_b);
}